// round 13
// baseline (speedup 1.0000x reference)
#include <cuda_runtime.h>
#include <math.h>

#define NPTS 65536
#define NN1  16384
#define NN2  8192
#define KNN  16

typedef unsigned long long u64;

__device__ __forceinline__ u64 pk2(float lo, float hi) {
    u64 r; asm("mov.b64 %0,{%1,%2};" : "=l"(r) : "f"(lo), "f"(hi)); return r;
}
__device__ __forceinline__ u64 pk1(float v) { return pk2(v, v); }
__device__ __forceinline__ float2 upk(u64 v) {
    float2 f; asm("mov.b64 {%0,%1},%2;" : "=f"(f.x), "=f"(f.y) : "l"(v)); return f;
}
__device__ __forceinline__ u64 ff2(u64 a, u64 b, u64 c) {
    u64 d; asm("fma.rn.f32x2 %0,%1,%2,%3;" : "=l"(d) : "l"(a), "l"(b), "l"(c)); return d;
}
__device__ __forceinline__ u64 add2(u64 a, u64 b) {
    u64 d; asm("add.rn.f32x2 %0,%1,%2;" : "=l"(d) : "l"(a), "l"(b)); return d;
}

// Intermediate activations (device globals — no allocation allowed)
__device__ float g_h  [NPTS * 32];
__device__ float g_hW1[(size_t)NPTS * 64];    // h @ Watt1_top (rows 0..31)
__device__ float g_h1 [(size_t)NN1 * 64];
__device__ float g_hW2[(size_t)NN1 * 128];    // h1 @ Watt2_top (rows 0..63)
__device__ float g_agg[(size_t)NN2 * 128];
__device__ float g_h2 [(size_t)NN2 * 128];

// ---------------------------------------------------------------------------
// down: h = relu(x @ W_down + b_down); hW1 = h @ Watt1_top (no bias/relu)
// ---------------------------------------------------------------------------
__global__ void __launch_bounds__(512)
down_kernel(const float* __restrict__ x,
            const float* __restrict__ W,
            const float* __restrict__ b,
            const float* __restrict__ Watt1) {
    __shared__ float sW[64 * 32];
    __shared__ float sWt[32 * 64];
    __shared__ float sb[32];
    int tid = threadIdx.x;
    for (int i = tid; i < 64 * 32; i += 512) { sW[i] = W[i]; sWt[i] = Watt1[i]; }
    if (tid < 32) sb[tid] = b[tid];
    __syncthreads();

    int p = blockIdx.x * 512 + tid;

    float xr[64];
    const float4* xp = (const float4*)(x + (size_t)p * 64);
#pragma unroll
    for (int i = 0; i < 16; i++) {
        float4 v = xp[i];
        xr[4*i+0] = v.x; xr[4*i+1] = v.y; xr[4*i+2] = v.z; xr[4*i+3] = v.w;
    }
    u64 acc[16];
#pragma unroll
    for (int j = 0; j < 16; j++) acc[j] = pk2(sb[2*j], sb[2*j+1]);
#pragma unroll 4
    for (int i = 0; i < 64; i++) {
        u64 xi = pk1(xr[i]);
        const u64* wr = (const u64*)&sW[i * 32];
#pragma unroll
        for (int j = 0; j < 16; j++) acc[j] = ff2(xi, wr[j], acc[j]);
    }
    float h[32];
    float* op = &g_h[(size_t)p * 32];
#pragma unroll
    for (int j = 0; j < 16; j++) {
        float2 v = upk(acc[j]);
        h[2*j]   = fmaxf(v.x, 0.f);
        h[2*j+1] = fmaxf(v.y, 0.f);
        op[2*j]   = h[2*j];
        op[2*j+1] = h[2*j+1];
    }
    u64* wop = (u64*)&g_hW1[(size_t)p * 64];
#pragma unroll
    for (int half = 0; half < 2; half++) {
        u64 acc2[16];
#pragma unroll
        for (int j = 0; j < 16; j++) acc2[j] = 0ull;
#pragma unroll 4
        for (int i = 0; i < 32; i++) {
            u64 xi = pk1(h[i]);
            const u64* wr = (const u64*)&sWt[i * 64 + half * 32];
#pragma unroll
            for (int j = 0; j < 16; j++) acc2[j] = ff2(xi, wr[j], acc2[j]);
        }
#pragma unroll
        for (int j = 0; j < 16; j++) wop[half * 16 + j] = acc2[j];
    }
}

// ---------------------------------------------------------------------------
// conv1: T=8 targets/iter, 512 threads, grid 296, occ 2.
// att accumulators init from g_hW1 via LDG; softmax stores exp in-place.
// ---------------------------------------------------------------------------
#define FT1  20
#define FT1A 18
#define SH1S 36
#define C1_DYN_FLOATS (320 + 2048 + 4096 + 8*32*FT1 + 8*64*FT1A + 8*16*SH1S)

__global__ void __launch_bounds__(512, 2)
conv1_kernel(const float* __restrict__ pos,
             const int*   __restrict__ idx1,
             const int*   __restrict__ src1,
             const float* __restrict__ Wpp, const float* __restrict__ bpp,
             const float* __restrict__ Watt, const float* __restrict__ batt,
             const float* __restrict__ Wg,  const float* __restrict__ bg) {
    extern __shared__ float smem[];
    float* sWpp  = smem;                        // 320
    float* sWattB= smem + 320;                  // 2048 (Watt rows 32..63)
    float* sWg   = smem + 2368;                 // 4096
    float* fijT  = smem + 6464;                 // 8*32*20 [t][rij feat][edge]
    float* attT  = smem + 6464 + 8*32*FT1;      // 8*64*18 [t][o][edge]
    float* sh    = smem + 6464 + 8*32*FT1 + 8*64*FT1A;  // 8*16*36 [et][feat]

    __shared__ float sbpp[32], sbatt[64], sbg[64];
    __shared__ float sv[128];
    __shared__ float aggS[8][64];
    __shared__ int   ssrc[128];

    int tid = threadIdx.x;
    for (int i = tid; i < 320; i += 512) sWpp[i] = Wpp[i];
    for (int i = tid; i < 2048; i += 512) sWattB[i] = Watt[32*64 + i];
    for (int i = tid; i < 4096; i += 512) sWg[i] = Wg[i];
    if (tid < 32) sbpp[tid] = bpp[tid];
    if (tid < 64) { sbatt[tid] = batt[tid]; sbg[tid] = bg[tid]; }
    __syncthreads();

    for (int t0 = blockIdx.x * 8; t0 < NN1; t0 += gridDim.x * 8) {
        // ---- gather: e fastest; h row-major + rij; record src ----
        {
            int e   = tid & 15;
            int r   = tid >> 4;      // 0..31
            int t   = r >> 2;        // 0..7
            int sub = r & 3;         // 0..3
            int et  = t * 16 + e;
            int tgt = t0 + t;
            int pi = idx1[tgt];
            float pix = pos[pi*3+0], piy = pos[pi*3+1], piz = pos[pi*3+2];
            int s = src1[tgt * KNN + e];
            if (sub == 0) ssrc[et] = s;
            float pjx = pos[s*3+0], pjy = pos[s*3+1], pjz = pos[s*3+2];
            float vx = pix - pjx, vy = piy - pjy, vz = piz - pjz;
            float rel[10];
            rel[0] = pix; rel[1] = piy; rel[2] = piz;
            rel[3] = pjx; rel[4] = pjy; rel[5] = pjz;
            rel[6] = vx;  rel[7] = vy;  rel[8] = vz;
            rel[9] = sqrtf(vx*vx + vy*vy + vz*vz);

            const float4* hp = (const float4*)&g_h[(size_t)s * 32 + sub * 8];
            float4* shp = (float4*)&sh[et * SH1S + sub * 8];
            shp[0] = hp[0]; shp[1] = hp[1];

#pragma unroll
            for (int k = 0; k < 8; k++) {
                int o = sub * 8 + k;
                float a = sbpp[o];
#pragma unroll
                for (int i = 0; i < 10; i++) a += rel[i] * sWpp[i * 32 + o];
                fijT[(t * 32 + o) * FT1 + e] = fmaxf(a, 0.f);
            }
        }
        __syncthreads();

        // ---- att: acc init from g_hW1 (LDG), then rij@WattB, +bias, relu ----
        {
            int t = tid >> 6;
            int q = (tid >> 2) & 15;
            int g = tid & 3;
            int eb = t * 16 + 4 * g;
            int s0 = ssrc[eb], s1 = ssrc[eb+1], s2 = ssrc[eb+2], s3 = ssrc[eb+3];
            float4 v0 = *(const float4*)&g_hW1[(size_t)s0 * 64 + 4*q];
            float4 v1 = *(const float4*)&g_hW1[(size_t)s1 * 64 + 4*q];
            float4 v2 = *(const float4*)&g_hW1[(size_t)s2 * 64 + 4*q];
            float4 v3 = *(const float4*)&g_hW1[(size_t)s3 * 64 + 4*q];
            u64 acc[8];
            acc[0] = pk2(v0.x, v1.x); acc[1] = pk2(v2.x, v3.x);
            acc[2] = pk2(v0.y, v1.y); acc[3] = pk2(v2.y, v3.y);
            acc[4] = pk2(v0.z, v1.z); acc[5] = pk2(v2.z, v3.z);
            acc[6] = pk2(v0.w, v1.w); acc[7] = pk2(v2.w, v3.w);

            const float4* W4 = (const float4*)sWattB;
            const float* fb = &fijT[(t * 32) * FT1 + 4 * g];
#pragma unroll 4
            for (int i = 0; i < 32; i++) {
                float4 w = W4[i * 16 + q];
                u64 w0 = pk1(w.x), w1 = pk1(w.y), w2 = pk1(w.z), w3 = pk1(w.w);
                ulonglong2 a = *(const ulonglong2*)(fb + i * FT1);
                acc[0] = ff2(a.x, w0, acc[0]); acc[1] = ff2(a.y, w0, acc[1]);
                acc[2] = ff2(a.x, w1, acc[2]); acc[3] = ff2(a.y, w1, acc[3]);
                acc[4] = ff2(a.x, w2, acc[4]); acc[5] = ff2(a.y, w2, acc[5]);
                acc[6] = ff2(a.x, w3, acc[6]); acc[7] = ff2(a.y, w3, acc[7]);
            }
            float* ab = &attT[(t * 64 + 4 * q) * FT1A + 4 * g];
#pragma unroll
            for (int j = 0; j < 4; j++) {
                u64 bb = pk1(sbatt[4*q + j]);
                float2 r0 = upk(add2(acc[j*2],   bb));
                float2 r1 = upk(add2(acc[j*2+1], bb));
                *(u64*)&ab[j*FT1A + 0] = pk2(fmaxf(r0.x, 0.f), fmaxf(r0.y, 0.f));
                *(u64*)&ab[j*FT1A + 2] = pk2(fmaxf(r1.x, 0.f), fmaxf(r1.y, 0.f));
            }
        }
        __syncthreads();

        // ---- softmax per edge: compute exp in-place, keep only 1/sum ----
        {
            int et = tid >> 2, c = tid & 3;
            float* ac = &attT[((et >> 4) * 64) * FT1A + (et & 15)];
            float m = -1e30f;
#pragma unroll 4
            for (int k = 0; k < 16; k++) m = fmaxf(m, ac[(c + 4*k)*FT1A]);
            m = fmaxf(m, __shfl_xor_sync(0xFFFFFFFFu, m, 1));
            m = fmaxf(m, __shfl_xor_sync(0xFFFFFFFFu, m, 2));
            float s = 0.f;
#pragma unroll 4
            for (int k = 0; k < 16; k++) {
                float ev = __expf(ac[(c + 4*k)*FT1A] - m);
                s += ev;
                ac[(c + 4*k)*FT1A] = ev;
            }
            s += __shfl_xor_sync(0xFFFFFFFFu, s, 1);
            s += __shfl_xor_sync(0xFFFFFFFFu, s, 2);
            if (c == 0) sv[et] = 1.f / s;
        }
        __syncthreads();

        // ---- agg[o] = sum_e (ev * inv_sum) * fij  (no exp here) ----
        {
            int t = tid >> 6, o = tid & 63;
            const float* ar = &attT[(t * 64 + o) * FT1A];
            float a = 0.f;
            if (o < 32) {
                const float* hb = &sh[(t * 16) * SH1S + o];
#pragma unroll
                for (int e = 0; e < 16; e++)
                    a += ar[e] * sv[t * 16 + e] * hb[e * SH1S];
            } else {
                const float* fr = &fijT[(t * 32 + (o - 32)) * FT1];
#pragma unroll
                for (int e = 0; e < 16; e++)
                    a += ar[e] * sv[t * 16 + e] * fr[e];
            }
            aggS[t][o] = a;
        }
        __syncthreads();

        // ---- global: h1 = relu(agg @ Wg + bg): (t8, op32, c2), shfl ----
        {
            int t = tid >> 6, op = (tid >> 1) & 31, c = tid & 1;
            u64 acc = 0ull;
#pragma unroll 4
            for (int ii = 0; ii < 32; ii++) {
                int i = c * 32 + ii;
                acc = ff2(pk1(aggS[t][i]), *(const u64*)&sWg[i*64 + 2*op], acc);
            }
            u64 other = __shfl_xor_sync(0xFFFFFFFFu, acc, 1);
            acc = add2(acc, other);
            if (c == 0) {
                float2 v = upk(acc);
                int o = 2 * op;
                float* opt = &g_h1[(size_t)(t0 + t) * 64 + o];
                opt[0] = fmaxf(v.x + sbg[o],   0.f);
                opt[1] = fmaxf(v.y + sbg[o+1], 0.f);
            }
        }
        __syncthreads();
    }
}

// ---------------------------------------------------------------------------
// gemm_hw2: g_hW2 = g_h1 @ Watt2_top  [16384,64]@[64,128]
// ---------------------------------------------------------------------------
#define GHW2_DYN_FLOATS (64*128 + 32*64)

__global__ void __launch_bounds__(512, 2)
gemm_hw2_kernel(const float* __restrict__ Watt2) {
    extern __shared__ float smem[];
    float* sW   = smem;
    float* sact = smem + 64*128;

    int tid = threadIdx.x;
    for (int i = tid; i < 64*128; i += 512) sW[i] = Watt2[i];
    __syncthreads();

    for (int t0 = blockIdx.x * 32; t0 < NN1; t0 += gridDim.x * 32) {
        ((float4*)sact)[tid] = ((const float4*)&g_h1[(size_t)t0 * 64])[tid];
        __syncthreads();

        int tg = tid >> 5;
        int q  = tid & 31;
        const float* a0p = &sact[(2*tg + 0) * 64];
        const float* a1p = &sact[(2*tg + 1) * 64];
        const float4* W4 = (const float4*)sW;

        u64 acc[4];
#pragma unroll
        for (int j = 0; j < 4; j++) acc[j] = 0ull;
#pragma unroll 4
        for (int i = 0; i < 64; i++) {
            float4 w = W4[i * 32 + q];
            u64 wlo = pk2(w.x, w.y), whi = pk2(w.z, w.w);
            u64 x0 = pk1(a0p[i]), x1 = pk1(a1p[i]);
            acc[0] = ff2(x0, wlo, acc[0]); acc[1] = ff2(x0, whi, acc[1]);
            acc[2] = ff2(x1, wlo, acc[2]); acc[3] = ff2(x1, whi, acc[3]);
        }
        int o = 4 * q;
        u64* o0 = (u64*)&g_hW2[(size_t)(t0 + 2*tg) * 128 + o];
        u64* o1 = (u64*)&g_hW2[(size_t)(t0 + 2*tg + 1) * 128 + o];
        o0[0] = acc[0]; o0[1] = acc[1];
        o1[0] = acc[2]; o1[1] = acc[3];
        __syncthreads();
    }
}

// ---------------------------------------------------------------------------
// conv2: T=4 targets/iter, 512 threads, grid 296, occ 2.
// att accumulators init from g_hW2 via LDG; softmax stores exp in-place.
// ---------------------------------------------------------------------------
#define FT2   20
#define FT2A  18
#define SH2S  68
#define C2_DYN_FLOATS (640 + 8192 + 4*64*FT2 + 4*128*FT2A + 4*16*SH2S)

__global__ void __launch_bounds__(512, 2)
conv2_kernel(const float* __restrict__ pos,
             const int*   __restrict__ idx1,
             const int*   __restrict__ idx2,
             const int*   __restrict__ src2,
             const float* __restrict__ Wpp, const float* __restrict__ bpp,
             const float* __restrict__ Watt, const float* __restrict__ batt) {
    extern __shared__ float smem[];
    float* sWpp  = smem;                                // 640
    float* sWattB= smem + 640;                          // 8192 (rows 64..127)
    float* fijT  = smem + 640 + 8192;                   // 4*64*20
    float* attT  = smem + 640 + 8192 + 4*64*FT2;        // 4*128*18
    float* sh1   = smem + 640 + 8192 + 4*64*FT2 + 4*128*FT2A;  // 4*16*68

    __shared__ float sbpp[64], sbatt[128];
    __shared__ float sv[64];
    __shared__ int   ssrc[64];

    int tid = threadIdx.x;
    for (int i = tid; i < 640; i += 512) sWpp[i] = Wpp[i];
    for (int i = tid; i < 8192; i += 512) sWattB[i] = Watt[64*128 + i];
    if (tid < 64)  sbpp[tid] = bpp[tid];
    if (tid < 128) sbatt[tid] = batt[tid];
    __syncthreads();

    for (int t0 = blockIdx.x * 4; t0 < NN2; t0 += gridDim.x * 4) {
        // ---- gather: e fastest; h1 row-major + rij; record src ----
        {
            int e   = tid & 15;
            int idx = tid >> 4;      // 0..31
            int t   = idx >> 3;      // 0..3
            int sub = idx & 7;       // 0..7
            int et  = t * 16 + e;
            int tgt = t0 + t;
            int pidx = idx1[idx2[tgt]];
            float pix = pos[pidx*3+0], piy = pos[pidx*3+1], piz = pos[pidx*3+2];
            int s = src2[tgt * KNN + e];
            if (sub == 0) ssrc[et] = s;
            int pj = idx1[s];
            float pjx = pos[pj*3+0], pjy = pos[pj*3+1], pjz = pos[pj*3+2];
            float vx = pix - pjx, vy = piy - pjy, vz = piz - pjz;
            float rel[10];
            rel[0] = pix; rel[1] = piy; rel[2] = piz;
            rel[3] = pjx; rel[4] = pjy; rel[5] = pjz;
            rel[6] = vx;  rel[7] = vy;  rel[8] = vz;
            rel[9] = sqrtf(vx*vx + vy*vy + vz*vz);

            const float4* hp = (const float4*)&g_h1[(size_t)s * 64 + sub * 8];
            float4* shp = (float4*)&sh1[et * SH2S + sub * 8];
            shp[0] = hp[0]; shp[1] = hp[1];

#pragma unroll
            for (int k = 0; k < 8; k++) {
                int o = sub * 8 + k;
                float a = sbpp[o];
#pragma unroll
                for (int i = 0; i < 10; i++) a += rel[i] * sWpp[i * 64 + o];
                fijT[(t * 64 + o) * FT2 + e] = fmaxf(a, 0.f);
            }
        }
        __syncthreads();

        // ---- att: acc init from g_hW2 (LDG), rij@WattB, +bias, relu ----
        {
            int g  = tid & 3;
            int ql = (tid >> 2) & 7;
            int t  = (tid >> 5) & 3;
            int qh = tid >> 7;           // 0..3
            int q  = ql + 8 * qh;        // 0..31
            int eb = t * 16 + 4 * g;
            int s0 = ssrc[eb], s1 = ssrc[eb+1], s2 = ssrc[eb+2], s3 = ssrc[eb+3];
            float4 v0 = *(const float4*)&g_hW2[(size_t)s0 * 128 + 4*q];
            float4 v1 = *(const float4*)&g_hW2[(size_t)s1 * 128 + 4*q];
            float4 v2 = *(const float4*)&g_hW2[(size_t)s2 * 128 + 4*q];
            float4 v3 = *(const float4*)&g_hW2[(size_t)s3 * 128 + 4*q];
            u64 acc[8];
            acc[0] = pk2(v0.x, v1.x); acc[1] = pk2(v2.x, v3.x);
            acc[2] = pk2(v0.y, v1.y); acc[3] = pk2(v2.y, v3.y);
            acc[4] = pk2(v0.z, v1.z); acc[5] = pk2(v2.z, v3.z);
            acc[6] = pk2(v0.w, v1.w); acc[7] = pk2(v2.w, v3.w);

            const float4* W4 = (const float4*)sWattB;
            const float* fb = &fijT[(t * 64) * FT2 + 4 * g];
#pragma unroll 4
            for (int i = 0; i < 64; i++) {
                float4 w = W4[i * 32 + q];
                u64 w0 = pk1(w.x), w1 = pk1(w.y), w2 = pk1(w.z), w3 = pk1(w.w);
                ulonglong2 a = *(const ulonglong2*)(fb + i * FT2);
                acc[0] = ff2(a.x, w0, acc[0]); acc[1] = ff2(a.y, w0, acc[1]);
                acc[2] = ff2(a.x, w1, acc[2]); acc[3] = ff2(a.y, w1, acc[3]);
                acc[4] = ff2(a.x, w2, acc[4]); acc[5] = ff2(a.y, w2, acc[5]);
                acc[6] = ff2(a.x, w3, acc[6]); acc[7] = ff2(a.y, w3, acc[7]);
            }
            float* ab = &attT[(t * 128 + 4 * q) * FT2A + 4 * g];
#pragma unroll
            for (int j = 0; j < 4; j++) {
                u64 bb = pk1(sbatt[4*q + j]);
                float2 r0 = upk(add2(acc[j*2],   bb));
                float2 r1 = upk(add2(acc[j*2+1], bb));
                *(u64*)&ab[j*FT2A + 0] = pk2(fmaxf(r0.x, 0.f), fmaxf(r0.y, 0.f));
                *(u64*)&ab[j*FT2A + 2] = pk2(fmaxf(r1.x, 0.f), fmaxf(r1.y, 0.f));
            }
        }
        __syncthreads();

        // ---- softmax per edge: compute exp in-place, keep only 1/sum ----
        {
            int et = tid >> 3, cc = tid & 7;
            float* ac = &attT[((et >> 4) * 128) * FT2A + (et & 15)];
            float m = -1e30f;
#pragma unroll 4
            for (int k = 0; k < 16; k++) m = fmaxf(m, ac[(cc + 8*k)*FT2A]);
            m = fmaxf(m, __shfl_xor_sync(0xFFFFFFFFu, m, 1));
            m = fmaxf(m, __shfl_xor_sync(0xFFFFFFFFu, m, 2));
            m = fmaxf(m, __shfl_xor_sync(0xFFFFFFFFu, m, 4));
            float s = 0.f;
#pragma unroll 4
            for (int k = 0; k < 16; k++) {
                float ev = __expf(ac[(cc + 8*k)*FT2A] - m);
                s += ev;
                ac[(cc + 8*k)*FT2A] = ev;
            }
            s += __shfl_xor_sync(0xFFFFFFFFu, s, 1);
            s += __shfl_xor_sync(0xFFFFFFFFu, s, 2);
            s += __shfl_xor_sync(0xFFFFFFFFu, s, 4);
            if (cc == 0) sv[et] = 1.f / s;
        }
        __syncthreads();

        // ---- agg -> global scratch (no exp; stored weights * inv_sum) ----
        {
            int t = tid >> 7, o = tid & 127;
            const float* ar = &attT[(t * 128 + o) * FT2A];
            float a = 0.f;
            if (o < 64) {
                const float* hb = &sh1[(t * 16) * SH2S + o];
#pragma unroll
                for (int e = 0; e < 16; e++)
                    a += ar[e] * sv[t * 16 + e] * hb[e * SH2S];
            } else {
                const float* fr = &fijT[(t * 64 + (o - 64)) * FT2];
#pragma unroll
                for (int e = 0; e < 16; e++)
                    a += ar[e] * sv[t * 16 + e] * fr[e];
            }
            g_agg[(size_t)(t0 + t) * 128 + o] = a;
        }
        __syncthreads();
    }
}

// ---------------------------------------------------------------------------
// gemm2: h2 = relu(g_agg @ Wg + bg). T=32, thread=(tg16,q32)x2 targets.
// ---------------------------------------------------------------------------
#define G2_DYN_FLOATS (128*128 + 32*128)

__global__ void __launch_bounds__(512, 2)
gemm2_kernel(const float* __restrict__ Wg, const float* __restrict__ bg) {
    extern __shared__ float smem[];
    float* sWg  = smem;
    float* sagg = smem + 16384;
    __shared__ float sbg[128];

    int tid = threadIdx.x;
    for (int i = tid; i < 16384; i += 512) sWg[i] = Wg[i];
    if (tid < 128) sbg[tid] = bg[tid];
    __syncthreads();

    for (int t0 = blockIdx.x * 32; t0 < NN2; t0 += gridDim.x * 32) {
#pragma unroll
        for (int k = 0; k < 8; k++)
            sagg[tid + 512*k] = g_agg[(size_t)t0 * 128 + tid + 512*k];
        __syncthreads();

        int tg = tid >> 5;
        int q  = tid & 31;
        const float* a0p = &sagg[(2*tg + 0) * 128];
        const float* a1p = &sagg[(2*tg + 1) * 128];
        const float4* W4 = (const float4*)sWg;

        u64 acc[4];
#pragma unroll
        for (int j = 0; j < 4; j++) acc[j] = 0ull;
#pragma unroll 4
        for (int i = 0; i < 128; i++) {
            float4 w = W4[i * 32 + q];
            u64 wlo = pk2(w.x, w.y), whi = pk2(w.z, w.w);
            u64 x0 = pk1(a0p[i]), x1 = pk1(a1p[i]);
            acc[0] = ff2(x0, wlo, acc[0]); acc[1] = ff2(x0, whi, acc[1]);
            acc[2] = ff2(x1, wlo, acc[2]); acc[3] = ff2(x1, whi, acc[3]);
        }
        int o = 4 * q;
        u64 bb0 = pk2(sbg[o], sbg[o+1]), bb1 = pk2(sbg[o+2], sbg[o+3]);
#pragma unroll
        for (int tt = 0; tt < 2; tt++) {
            float2 v0 = upk(add2(acc[tt*2],   bb0));
            float2 v1 = upk(add2(acc[tt*2+1], bb1));
            float* op = &g_h2[(size_t)(t0 + 2*tg + tt) * 128 + o];
            op[0] = fmaxf(v0.x, 0.f);
            op[1] = fmaxf(v0.y, 0.f);
            op[2] = fmaxf(v1.x, 0.f);
            op[3] = fmaxf(v1.y, 0.f);
        }
        __syncthreads();
    }
}

// ---------------------------------------------------------------------------
// tail: T=16 targets/iter, thread=(pair8, q32, ihalf2), float4 weights,
// 2 targets per thread, shfl-xor(1) half-reduce. 512 threads, grid 296.
// ---------------------------------------------------------------------------
#define TAIL_DYN_FLOATS (128*128 + 64*128 + 16*128 + 16*64)

__global__ void __launch_bounds__(512, 2)
tail_kernel(const float* __restrict__ x,
            const int*   __restrict__ idx1,
            const int*   __restrict__ idx2,
            const float* __restrict__ Wup, const float* __restrict__ bup,
            const float* __restrict__ Wsc, const float* __restrict__ bsc,
            float* __restrict__ out) {
    extern __shared__ float smem[];
    float* sWup = smem;                       // 16384
    float* sWsc = smem + 16384;               // 8192
    float* sh2  = smem + 24576;               // 16*128
    float* sx   = smem + 24576 + 16*128;      // 16*64

    __shared__ float sbup[128], sbsc[128];

    int tid = threadIdx.x;
    for (int i = tid; i < 16384; i += 512) sWup[i] = Wup[i];
    for (int i = tid; i < 8192;  i += 512) sWsc[i] = Wsc[i];
    if (tid < 128) { sbup[tid] = bup[tid]; sbsc[tid] = bsc[tid]; }
    __syncthreads();

    const float4* Wu4 = (const float4*)sWup;
    const float4* Ws4 = (const float4*)sWsc;

    for (int t0 = blockIdx.x * 16; t0 < NN2; t0 += gridDim.x * 16) {
#pragma unroll
        for (int k = 0; k < 4; k++)
            sh2[tid + 512*k] = g_h2[(size_t)t0 * 128 + tid + 512*k];
        {
            int t = tid >> 5, f2 = tid & 31;
            int xr = idx1[idx2[t0 + t]];
            const float2* xp = (const float2*)&x[(size_t)xr * 64];
            ((float2*)&sx[t * 64])[f2] = xp[f2];
        }
        __syncthreads();

        int tg = tid >> 6;             // 8 pairs (2 targets each)
        int q  = (tid >> 1) & 31;      // 4 outputs
        int c  = tid & 1;              // i-half
        const float* h0 = &sh2[(2*tg + 0) * 128];
        const float* h1 = &sh2[(2*tg + 1) * 128];
        const float* x0 = &sx[(2*tg + 0) * 64];
        const float* x1 = &sx[(2*tg + 1) * 64];

        u64 ua[4], sa[4];
#pragma unroll
        for (int j = 0; j < 4; j++) { ua[j] = 0ull; sa[j] = 0ull; }
#pragma unroll 4
        for (int ii = 0; ii < 64; ii++) {
            int i = c * 64 + ii;
            float4 w = Wu4[i * 32 + q];
            u64 wlo = pk2(w.x, w.y), whi = pk2(w.z, w.w);
            u64 a0 = pk1(h0[i]), a1 = pk1(h1[i]);
            ua[0] = ff2(a0, wlo, ua[0]); ua[1] = ff2(a0, whi, ua[1]);
            ua[2] = ff2(a1, wlo, ua[2]); ua[3] = ff2(a1, whi, ua[3]);
        }
#pragma unroll 4
        for (int ii = 0; ii < 32; ii++) {
            int i = c * 32 + ii;
            float4 w = Ws4[i * 32 + q];
            u64 wlo = pk2(w.x, w.y), whi = pk2(w.z, w.w);
            u64 a0 = pk1(x0[i]), a1 = pk1(x1[i]);
            sa[0] = ff2(a0, wlo, sa[0]); sa[1] = ff2(a0, whi, sa[1]);
            sa[2] = ff2(a1, wlo, sa[2]); sa[3] = ff2(a1, whi, sa[3]);
        }
#pragma unroll
        for (int j = 0; j < 4; j++) {
            ua[j] = add2(ua[j], __shfl_xor_sync(0xFFFFFFFFu, ua[j], 1));
            sa[j] = add2(sa[j], __shfl_xor_sync(0xFFFFFFFFu, sa[j], 1));
        }
        if (c == 0) {
            int o = 4 * q;
            u64 bu0 = pk2(sbup[o], sbup[o+1]), bu1 = pk2(sbup[o+2], sbup[o+3]);
            u64 bs0 = pk2(sbsc[o], sbsc[o+1]), bs1 = pk2(sbsc[o+2], sbsc[o+3]);
#pragma unroll
            for (int tt = 0; tt < 2; tt++) {
                float2 a0 = upk(add2(ua[tt*2],   bu0));
                float2 a1 = upk(add2(ua[tt*2+1], bu1));
                float2 c0 = upk(add2(sa[tt*2],   bs0));
                float2 c1 = upk(add2(sa[tt*2+1], bs1));
                float* opt = &out[(size_t)(t0 + 2*tg + tt) * 128 + o];
                opt[0] = fmaxf(fmaxf(a0.x, 0.f) + fmaxf(c0.x, 0.f), 0.f);
                opt[1] = fmaxf(fmaxf(a0.y, 0.f) + fmaxf(c0.y, 0.f), 0.f);
                opt[2] = fmaxf(fmaxf(a1.x, 0.f) + fmaxf(c1.x, 0.f), 0.f);
                opt[3] = fmaxf(fmaxf(a1.y, 0.f) + fmaxf(c1.y, 0.f), 0.f);
            }
        }
        __syncthreads();
    }
}

// ---------------------------------------------------------------------------
extern "C" void kernel_launch(void* const* d_in, const int* in_sizes, int n_in,
                              void* d_out, int out_size) {
    const float* x      = (const float*)d_in[0];
    const float* pos    = (const float*)d_in[1];
    const float* W_down = (const float*)d_in[2];
    const float* b_down = (const float*)d_in[3];
    const float* W_pp1  = (const float*)d_in[4];
    const float* b_pp1  = (const float*)d_in[5];
    const float* W_att1 = (const float*)d_in[6];
    const float* b_att1 = (const float*)d_in[7];
    const float* W_g1   = (const float*)d_in[8];
    const float* b_g1   = (const float*)d_in[9];
    const float* W_pp2  = (const float*)d_in[10];
    const float* b_pp2  = (const float*)d_in[11];
    const float* W_att2 = (const float*)d_in[12];
    const float* b_att2 = (const float*)d_in[13];
    const float* W_g2   = (const float*)d_in[14];
    const float* b_g2   = (const float*)d_in[15];
    const float* W_up   = (const float*)d_in[16];
    const float* b_up   = (const float*)d_in[17];
    const float* W_sc   = (const float*)d_in[18];
    const float* b_sc   = (const float*)d_in[19];
    const int*   idx1   = (const int*)d_in[20];
    const int*   idx2   = (const int*)d_in[21];
    const int*   src1   = (const int*)d_in[22];
    const int*   src2   = (const int*)d_in[24];
    float* out = (float*)d_out;

    cudaFuncSetAttribute(conv1_kernel, cudaFuncAttributeMaxDynamicSharedMemorySize,
                         C1_DYN_FLOATS * (int)sizeof(float));
    cudaFuncSetAttribute(gemm_hw2_kernel, cudaFuncAttributeMaxDynamicSharedMemorySize,
                         GHW2_DYN_FLOATS * (int)sizeof(float));
    cudaFuncSetAttribute(conv2_kernel, cudaFuncAttributeMaxDynamicSharedMemorySize,
                         C2_DYN_FLOATS * (int)sizeof(float));
    cudaFuncSetAttribute(gemm2_kernel, cudaFuncAttributeMaxDynamicSharedMemorySize,
                         G2_DYN_FLOATS * (int)sizeof(float));
    cudaFuncSetAttribute(tail_kernel, cudaFuncAttributeMaxDynamicSharedMemorySize,
                         TAIL_DYN_FLOATS * (int)sizeof(float));

    down_kernel<<<128, 512>>>(x, W_down, b_down, W_att1);
    conv1_kernel<<<296, 512, C1_DYN_FLOATS * sizeof(float)>>>(
        pos, idx1, src1, W_pp1, b_pp1, W_att1, b_att1, W_g1, b_g1);
    gemm_hw2_kernel<<<296, 512, GHW2_DYN_FLOATS * sizeof(float)>>>(W_att2);
    conv2_kernel<<<296, 512, C2_DYN_FLOATS * sizeof(float)>>>(
        pos, idx1, idx2, src2, W_pp2, b_pp2, W_att2, b_att2);
    gemm2_kernel<<<296, 512, G2_DYN_FLOATS * sizeof(float)>>>(W_g2, b_g2);
    tail_kernel<<<296, 512, TAIL_DYN_FLOATS * sizeof(float)>>>(
        x, idx1, idx2, W_up, b_up, W_sc, b_sc, out);
}

// round 14
// speedup vs baseline: 1.0356x; 1.0356x over previous
#include <cuda_runtime.h>
#include <math.h>

#define NPTS 65536
#define NN1  16384
#define NN2  8192
#define KNN  16

typedef unsigned long long u64;

__device__ __forceinline__ u64 pk2(float lo, float hi) {
    u64 r; asm("mov.b64 %0,{%1,%2};" : "=l"(r) : "f"(lo), "f"(hi)); return r;
}
__device__ __forceinline__ u64 pk1(float v) { return pk2(v, v); }
__device__ __forceinline__ float2 upk(u64 v) {
    float2 f; asm("mov.b64 {%0,%1},%2;" : "=f"(f.x), "=f"(f.y) : "l"(v)); return f;
}
__device__ __forceinline__ u64 ff2(u64 a, u64 b, u64 c) {
    u64 d; asm("fma.rn.f32x2 %0,%1,%2,%3;" : "=l"(d) : "l"(a), "l"(b), "l"(c)); return d;
}
__device__ __forceinline__ u64 add2(u64 a, u64 b) {
    u64 d; asm("add.rn.f32x2 %0,%1,%2;" : "=l"(d) : "l"(a), "l"(b)); return d;
}

// Intermediate activations (device globals — no allocation allowed)
__device__ float g_h  [NPTS * 32];
__device__ float g_hW1[(size_t)NPTS * 64];    // h @ Watt1_top (rows 0..31)
__device__ float g_h1 [(size_t)NN1 * 64];
__device__ float g_hW2[(size_t)NN1 * 128];    // h1 @ Watt2_top (rows 0..63)
__device__ float g_agg[(size_t)NN2 * 128];
__device__ float g_h2 [(size_t)NN2 * 128];

// ---------------------------------------------------------------------------
// down: h = relu(x @ W_down + b_down); hW1 = h @ Watt1_top (no bias/relu)
// ---------------------------------------------------------------------------
__global__ void __launch_bounds__(512)
down_kernel(const float* __restrict__ x,
            const float* __restrict__ W,
            const float* __restrict__ b,
            const float* __restrict__ Watt1) {
    __shared__ float sW[64 * 32];
    __shared__ float sWt[32 * 64];
    __shared__ float sb[32];
    int tid = threadIdx.x;
    for (int i = tid; i < 64 * 32; i += 512) { sW[i] = W[i]; sWt[i] = Watt1[i]; }
    if (tid < 32) sb[tid] = b[tid];
    __syncthreads();

    int p = blockIdx.x * 512 + tid;

    float xr[64];
    const float4* xp = (const float4*)(x + (size_t)p * 64);
#pragma unroll
    for (int i = 0; i < 16; i++) {
        float4 v = xp[i];
        xr[4*i+0] = v.x; xr[4*i+1] = v.y; xr[4*i+2] = v.z; xr[4*i+3] = v.w;
    }
    u64 acc[16];
#pragma unroll
    for (int j = 0; j < 16; j++) acc[j] = pk2(sb[2*j], sb[2*j+1]);
#pragma unroll 4
    for (int i = 0; i < 64; i++) {
        u64 xi = pk1(xr[i]);
        const u64* wr = (const u64*)&sW[i * 32];
#pragma unroll
        for (int j = 0; j < 16; j++) acc[j] = ff2(xi, wr[j], acc[j]);
    }
    float h[32];
    float* op = &g_h[(size_t)p * 32];
#pragma unroll
    for (int j = 0; j < 16; j++) {
        float2 v = upk(acc[j]);
        h[2*j]   = fmaxf(v.x, 0.f);
        h[2*j+1] = fmaxf(v.y, 0.f);
        op[2*j]   = h[2*j];
        op[2*j+1] = h[2*j+1];
    }
    u64* wop = (u64*)&g_hW1[(size_t)p * 64];
#pragma unroll
    for (int half = 0; half < 2; half++) {
        u64 acc2[16];
#pragma unroll
        for (int j = 0; j < 16; j++) acc2[j] = 0ull;
#pragma unroll 4
        for (int i = 0; i < 32; i++) {
            u64 xi = pk1(h[i]);
            const u64* wr = (const u64*)&sWt[i * 64 + half * 32];
#pragma unroll
            for (int j = 0; j < 16; j++) acc2[j] = ff2(xi, wr[j], acc2[j]);
        }
#pragma unroll
        for (int j = 0; j < 16; j++) wop[half * 16 + j] = acc2[j];
    }
}

// ---------------------------------------------------------------------------
// conv1: T=8 targets/iter, 512 threads, grid 296, occ 2.
// att: FFMA loop first, hW LDG values added after (latency hidden).
// Softmax: single pass, no max subtraction.
// ---------------------------------------------------------------------------
#define FT1  20
#define FT1A 18
#define SH1S 36
#define C1_DYN_FLOATS (320 + 2048 + 4096 + 8*32*FT1 + 8*64*FT1A + 8*16*SH1S)

__global__ void __launch_bounds__(512, 2)
conv1_kernel(const float* __restrict__ pos,
             const int*   __restrict__ idx1,
             const int*   __restrict__ src1,
             const float* __restrict__ Wpp, const float* __restrict__ bpp,
             const float* __restrict__ Watt, const float* __restrict__ batt,
             const float* __restrict__ Wg,  const float* __restrict__ bg) {
    extern __shared__ float smem[];
    float* sWpp  = smem;                        // 320
    float* sWattB= smem + 320;                  // 2048 (Watt rows 32..63)
    float* sWg   = smem + 2368;                 // 4096
    float* fijT  = smem + 6464;                 // 8*32*20 [t][rij feat][edge]
    float* attT  = smem + 6464 + 8*32*FT1;      // 8*64*18 [t][o][edge]
    float* sh    = smem + 6464 + 8*32*FT1 + 8*64*FT1A;  // 8*16*36 [et][feat]

    __shared__ float sbpp[32], sbatt[64], sbg[64];
    __shared__ float sv[128];
    __shared__ float aggS[8][64];
    __shared__ int   ssrc[128];

    int tid = threadIdx.x;
    for (int i = tid; i < 320; i += 512) sWpp[i] = Wpp[i];
    for (int i = tid; i < 2048; i += 512) sWattB[i] = Watt[32*64 + i];
    for (int i = tid; i < 4096; i += 512) sWg[i] = Wg[i];
    if (tid < 32) sbpp[tid] = bpp[tid];
    if (tid < 64) { sbatt[tid] = batt[tid]; sbg[tid] = bg[tid]; }
    __syncthreads();

    for (int t0 = blockIdx.x * 8; t0 < NN1; t0 += gridDim.x * 8) {
        // ---- gather: e fastest; h row-major + rij; record src ----
        {
            int e   = tid & 15;
            int r   = tid >> 4;      // 0..31
            int t   = r >> 2;        // 0..7
            int sub = r & 3;         // 0..3
            int et  = t * 16 + e;
            int tgt = t0 + t;
            int pi = idx1[tgt];
            float pix = pos[pi*3+0], piy = pos[pi*3+1], piz = pos[pi*3+2];
            int s = src1[tgt * KNN + e];
            if (sub == 0) ssrc[et] = s;
            float pjx = pos[s*3+0], pjy = pos[s*3+1], pjz = pos[s*3+2];
            float vx = pix - pjx, vy = piy - pjy, vz = piz - pjz;
            float rel[10];
            rel[0] = pix; rel[1] = piy; rel[2] = piz;
            rel[3] = pjx; rel[4] = pjy; rel[5] = pjz;
            rel[6] = vx;  rel[7] = vy;  rel[8] = vz;
            rel[9] = sqrtf(vx*vx + vy*vy + vz*vz);

            const float4* hp = (const float4*)&g_h[(size_t)s * 32 + sub * 8];
            float4* shp = (float4*)&sh[et * SH1S + sub * 8];
            shp[0] = hp[0]; shp[1] = hp[1];

#pragma unroll
            for (int k = 0; k < 8; k++) {
                int o = sub * 8 + k;
                float a = sbpp[o];
#pragma unroll
                for (int i = 0; i < 10; i++) a += rel[i] * sWpp[i * 32 + o];
                fijT[(t * 32 + o) * FT1 + e] = fmaxf(a, 0.f);
            }
        }
        __syncthreads();

        // ---- att: LDG issued first, FFMA loop, hW added after (hidden) ----
        {
            int t = tid >> 6;
            int q = (tid >> 2) & 15;
            int g = tid & 3;
            int eb = t * 16 + 4 * g;
            int s0 = ssrc[eb], s1 = ssrc[eb+1], s2 = ssrc[eb+2], s3 = ssrc[eb+3];
            float4 v0 = *(const float4*)&g_hW1[(size_t)s0 * 64 + 4*q];
            float4 v1 = *(const float4*)&g_hW1[(size_t)s1 * 64 + 4*q];
            float4 v2 = *(const float4*)&g_hW1[(size_t)s2 * 64 + 4*q];
            float4 v3 = *(const float4*)&g_hW1[(size_t)s3 * 64 + 4*q];

            u64 acc[8];
#pragma unroll
            for (int j = 0; j < 8; j++) acc[j] = 0ull;
            const float4* W4 = (const float4*)sWattB;
            const float* fb = &fijT[(t * 32) * FT1 + 4 * g];
#pragma unroll 4
            for (int i = 0; i < 32; i++) {
                float4 w = W4[i * 16 + q];
                u64 w0 = pk1(w.x), w1 = pk1(w.y), w2 = pk1(w.z), w3 = pk1(w.w);
                ulonglong2 a = *(const ulonglong2*)(fb + i * FT1);
                acc[0] = ff2(a.x, w0, acc[0]); acc[1] = ff2(a.y, w0, acc[1]);
                acc[2] = ff2(a.x, w1, acc[2]); acc[3] = ff2(a.y, w1, acc[3]);
                acc[4] = ff2(a.x, w2, acc[4]); acc[5] = ff2(a.y, w2, acc[5]);
                acc[6] = ff2(a.x, w3, acc[6]); acc[7] = ff2(a.y, w3, acc[7]);
            }
            // add deferred hW init + bias, relu, store
            acc[0] = add2(acc[0], pk2(v0.x, v1.x)); acc[1] = add2(acc[1], pk2(v2.x, v3.x));
            acc[2] = add2(acc[2], pk2(v0.y, v1.y)); acc[3] = add2(acc[3], pk2(v2.y, v3.y));
            acc[4] = add2(acc[4], pk2(v0.z, v1.z)); acc[5] = add2(acc[5], pk2(v2.z, v3.z));
            acc[6] = add2(acc[6], pk2(v0.w, v1.w)); acc[7] = add2(acc[7], pk2(v2.w, v3.w));
            float* ab = &attT[(t * 64 + 4 * q) * FT1A + 4 * g];
#pragma unroll
            for (int j = 0; j < 4; j++) {
                u64 bb = pk1(sbatt[4*q + j]);
                float2 r0 = upk(add2(acc[j*2],   bb));
                float2 r1 = upk(add2(acc[j*2+1], bb));
                *(u64*)&ab[j*FT1A + 0] = pk2(fmaxf(r0.x, 0.f), fmaxf(r0.y, 0.f));
                *(u64*)&ab[j*FT1A + 2] = pk2(fmaxf(r1.x, 0.f), fmaxf(r1.y, 0.f));
            }
        }
        __syncthreads();

        // ---- softmax per edge: single pass, no max; exp stored in place ----
        {
            int et = tid >> 2, c = tid & 3;
            float* ac = &attT[((et >> 4) * 64) * FT1A + (et & 15)];
            float s = 0.f;
#pragma unroll 4
            for (int k = 0; k < 16; k++) {
                float ev = __expf(ac[(c + 4*k)*FT1A]);
                s += ev;
                ac[(c + 4*k)*FT1A] = ev;
            }
            s += __shfl_xor_sync(0xFFFFFFFFu, s, 1);
            s += __shfl_xor_sync(0xFFFFFFFFu, s, 2);
            if (c == 0) sv[et] = 1.f / s;
        }
        __syncthreads();

        // ---- agg[o] = sum_e (ev * inv_sum) * fij ----
        {
            int t = tid >> 6, o = tid & 63;
            const float* ar = &attT[(t * 64 + o) * FT1A];
            float a = 0.f;
            if (o < 32) {
                const float* hb = &sh[(t * 16) * SH1S + o];
#pragma unroll
                for (int e = 0; e < 16; e++)
                    a += ar[e] * sv[t * 16 + e] * hb[e * SH1S];
            } else {
                const float* fr = &fijT[(t * 32 + (o - 32)) * FT1];
#pragma unroll
                for (int e = 0; e < 16; e++)
                    a += ar[e] * sv[t * 16 + e] * fr[e];
            }
            aggS[t][o] = a;
        }
        __syncthreads();

        // ---- global: h1 = relu(agg @ Wg + bg): (t8, op32, c2), shfl ----
        {
            int t = tid >> 6, op = (tid >> 1) & 31, c = tid & 1;
            u64 acc = 0ull;
#pragma unroll 4
            for (int ii = 0; ii < 32; ii++) {
                int i = c * 32 + ii;
                acc = ff2(pk1(aggS[t][i]), *(const u64*)&sWg[i*64 + 2*op], acc);
            }
            u64 other = __shfl_xor_sync(0xFFFFFFFFu, acc, 1);
            acc = add2(acc, other);
            if (c == 0) {
                float2 v = upk(acc);
                int o = 2 * op;
                float* opt = &g_h1[(size_t)(t0 + t) * 64 + o];
                opt[0] = fmaxf(v.x + sbg[o],   0.f);
                opt[1] = fmaxf(v.y + sbg[o+1], 0.f);
            }
        }
        __syncthreads();
    }
}

// ---------------------------------------------------------------------------
// gemm_hw2: g_hW2 = g_h1 @ Watt2_top  [16384,64]@[64,128]
// ---------------------------------------------------------------------------
#define GHW2_DYN_FLOATS (64*128 + 32*64)

__global__ void __launch_bounds__(512, 2)
gemm_hw2_kernel(const float* __restrict__ Watt2) {
    extern __shared__ float smem[];
    float* sW   = smem;
    float* sact = smem + 64*128;

    int tid = threadIdx.x;
    for (int i = tid; i < 64*128; i += 512) sW[i] = Watt2[i];
    __syncthreads();

    for (int t0 = blockIdx.x * 32; t0 < NN1; t0 += gridDim.x * 32) {
        ((float4*)sact)[tid] = ((const float4*)&g_h1[(size_t)t0 * 64])[tid];
        __syncthreads();

        int tg = tid >> 5;
        int q  = tid & 31;
        const float* a0p = &sact[(2*tg + 0) * 64];
        const float* a1p = &sact[(2*tg + 1) * 64];
        const float4* W4 = (const float4*)sW;

        u64 acc[4];
#pragma unroll
        for (int j = 0; j < 4; j++) acc[j] = 0ull;
#pragma unroll 4
        for (int i = 0; i < 64; i++) {
            float4 w = W4[i * 32 + q];
            u64 wlo = pk2(w.x, w.y), whi = pk2(w.z, w.w);
            u64 x0 = pk1(a0p[i]), x1 = pk1(a1p[i]);
            acc[0] = ff2(x0, wlo, acc[0]); acc[1] = ff2(x0, whi, acc[1]);
            acc[2] = ff2(x1, wlo, acc[2]); acc[3] = ff2(x1, whi, acc[3]);
        }
        int o = 4 * q;
        u64* o0 = (u64*)&g_hW2[(size_t)(t0 + 2*tg) * 128 + o];
        u64* o1 = (u64*)&g_hW2[(size_t)(t0 + 2*tg + 1) * 128 + o];
        o0[0] = acc[0]; o0[1] = acc[1];
        o1[0] = acc[2]; o1[1] = acc[3];
        __syncthreads();
    }
}

// ---------------------------------------------------------------------------
// conv2: T=4 targets/iter, 512 threads, grid 296, occ 2.
// att: FFMA loop first, hW LDG added after. Softmax single pass, no max.
// ---------------------------------------------------------------------------
#define FT2   20
#define FT2A  18
#define SH2S  68
#define C2_DYN_FLOATS (640 + 8192 + 4*64*FT2 + 4*128*FT2A + 4*16*SH2S)

__global__ void __launch_bounds__(512, 2)
conv2_kernel(const float* __restrict__ pos,
             const int*   __restrict__ idx1,
             const int*   __restrict__ idx2,
             const int*   __restrict__ src2,
             const float* __restrict__ Wpp, const float* __restrict__ bpp,
             const float* __restrict__ Watt, const float* __restrict__ batt) {
    extern __shared__ float smem[];
    float* sWpp  = smem;                                // 640
    float* sWattB= smem + 640;                          // 8192 (rows 64..127)
    float* fijT  = smem + 640 + 8192;                   // 4*64*20
    float* attT  = smem + 640 + 8192 + 4*64*FT2;        // 4*128*18
    float* sh1   = smem + 640 + 8192 + 4*64*FT2 + 4*128*FT2A;  // 4*16*68

    __shared__ float sbpp[64], sbatt[128];
    __shared__ float sv[64];
    __shared__ int   ssrc[64];

    int tid = threadIdx.x;
    for (int i = tid; i < 640; i += 512) sWpp[i] = Wpp[i];
    for (int i = tid; i < 8192; i += 512) sWattB[i] = Watt[64*128 + i];
    if (tid < 64)  sbpp[tid] = bpp[tid];
    if (tid < 128) sbatt[tid] = batt[tid];
    __syncthreads();

    for (int t0 = blockIdx.x * 4; t0 < NN2; t0 += gridDim.x * 4) {
        // ---- gather: e fastest; h1 row-major + rij; record src ----
        {
            int e   = tid & 15;
            int idx = tid >> 4;      // 0..31
            int t   = idx >> 3;      // 0..3
            int sub = idx & 7;       // 0..7
            int et  = t * 16 + e;
            int tgt = t0 + t;
            int pidx = idx1[idx2[tgt]];
            float pix = pos[pidx*3+0], piy = pos[pidx*3+1], piz = pos[pidx*3+2];
            int s = src2[tgt * KNN + e];
            if (sub == 0) ssrc[et] = s;
            int pj = idx1[s];
            float pjx = pos[pj*3+0], pjy = pos[pj*3+1], pjz = pos[pj*3+2];
            float vx = pix - pjx, vy = piy - pjy, vz = piz - pjz;
            float rel[10];
            rel[0] = pix; rel[1] = piy; rel[2] = piz;
            rel[3] = pjx; rel[4] = pjy; rel[5] = pjz;
            rel[6] = vx;  rel[7] = vy;  rel[8] = vz;
            rel[9] = sqrtf(vx*vx + vy*vy + vz*vz);

            const float4* hp = (const float4*)&g_h1[(size_t)s * 64 + sub * 8];
            float4* shp = (float4*)&sh1[et * SH2S + sub * 8];
            shp[0] = hp[0]; shp[1] = hp[1];

#pragma unroll
            for (int k = 0; k < 8; k++) {
                int o = sub * 8 + k;
                float a = sbpp[o];
#pragma unroll
                for (int i = 0; i < 10; i++) a += rel[i] * sWpp[i * 64 + o];
                fijT[(t * 64 + o) * FT2 + e] = fmaxf(a, 0.f);
            }
        }
        __syncthreads();

        // ---- att: LDG issued first, FFMA loop, hW added after (hidden) ----
        {
            int g  = tid & 3;
            int ql = (tid >> 2) & 7;
            int t  = (tid >> 5) & 3;
            int qh = tid >> 7;           // 0..3
            int q  = ql + 8 * qh;        // 0..31
            int eb = t * 16 + 4 * g;
            int s0 = ssrc[eb], s1 = ssrc[eb+1], s2 = ssrc[eb+2], s3 = ssrc[eb+3];
            float4 v0 = *(const float4*)&g_hW2[(size_t)s0 * 128 + 4*q];
            float4 v1 = *(const float4*)&g_hW2[(size_t)s1 * 128 + 4*q];
            float4 v2 = *(const float4*)&g_hW2[(size_t)s2 * 128 + 4*q];
            float4 v3 = *(const float4*)&g_hW2[(size_t)s3 * 128 + 4*q];

            u64 acc[8];
#pragma unroll
            for (int j = 0; j < 8; j++) acc[j] = 0ull;
            const float4* W4 = (const float4*)sWattB;
            const float* fb = &fijT[(t * 64) * FT2 + 4 * g];
#pragma unroll 4
            for (int i = 0; i < 64; i++) {
                float4 w = W4[i * 32 + q];
                u64 w0 = pk1(w.x), w1 = pk1(w.y), w2 = pk1(w.z), w3 = pk1(w.w);
                ulonglong2 a = *(const ulonglong2*)(fb + i * FT2);
                acc[0] = ff2(a.x, w0, acc[0]); acc[1] = ff2(a.y, w0, acc[1]);
                acc[2] = ff2(a.x, w1, acc[2]); acc[3] = ff2(a.y, w1, acc[3]);
                acc[4] = ff2(a.x, w2, acc[4]); acc[5] = ff2(a.y, w2, acc[5]);
                acc[6] = ff2(a.x, w3, acc[6]); acc[7] = ff2(a.y, w3, acc[7]);
            }
            acc[0] = add2(acc[0], pk2(v0.x, v1.x)); acc[1] = add2(acc[1], pk2(v2.x, v3.x));
            acc[2] = add2(acc[2], pk2(v0.y, v1.y)); acc[3] = add2(acc[3], pk2(v2.y, v3.y));
            acc[4] = add2(acc[4], pk2(v0.z, v1.z)); acc[5] = add2(acc[5], pk2(v2.z, v3.z));
            acc[6] = add2(acc[6], pk2(v0.w, v1.w)); acc[7] = add2(acc[7], pk2(v2.w, v3.w));
            float* ab = &attT[(t * 128 + 4 * q) * FT2A + 4 * g];
#pragma unroll
            for (int j = 0; j < 4; j++) {
                u64 bb = pk1(sbatt[4*q + j]);
                float2 r0 = upk(add2(acc[j*2],   bb));
                float2 r1 = upk(add2(acc[j*2+1], bb));
                *(u64*)&ab[j*FT2A + 0] = pk2(fmaxf(r0.x, 0.f), fmaxf(r0.y, 0.f));
                *(u64*)&ab[j*FT2A + 2] = pk2(fmaxf(r1.x, 0.f), fmaxf(r1.y, 0.f));
            }
        }
        __syncthreads();

        // ---- softmax per edge: single pass, no max; exp stored in place ----
        {
            int et = tid >> 3, cc = tid & 7;
            float* ac = &attT[((et >> 4) * 128) * FT2A + (et & 15)];
            float s = 0.f;
#pragma unroll 4
            for (int k = 0; k < 16; k++) {
                float ev = __expf(ac[(cc + 8*k)*FT2A]);
                s += ev;
                ac[(cc + 8*k)*FT2A] = ev;
            }
            s += __shfl_xor_sync(0xFFFFFFFFu, s, 1);
            s += __shfl_xor_sync(0xFFFFFFFFu, s, 2);
            s += __shfl_xor_sync(0xFFFFFFFFu, s, 4);
            if (cc == 0) sv[et] = 1.f / s;
        }
        __syncthreads();

        // ---- agg -> global scratch ----
        {
            int t = tid >> 7, o = tid & 127;
            const float* ar = &attT[(t * 128 + o) * FT2A];
            float a = 0.f;
            if (o < 64) {
                const float* hb = &sh1[(t * 16) * SH2S + o];
#pragma unroll
                for (int e = 0; e < 16; e++)
                    a += ar[e] * sv[t * 16 + e] * hb[e * SH2S];
            } else {
                const float* fr = &fijT[(t * 64 + (o - 64)) * FT2];
#pragma unroll
                for (int e = 0; e < 16; e++)
                    a += ar[e] * sv[t * 16 + e] * fr[e];
            }
            g_agg[(size_t)(t0 + t) * 128 + o] = a;
        }
        __syncthreads();
    }
}

// ---------------------------------------------------------------------------
// gemm2: h2 = relu(g_agg @ Wg + bg). T=32, thread=(tg16,q32)x2 targets.
// ---------------------------------------------------------------------------
#define G2_DYN_FLOATS (128*128 + 32*128)

__global__ void __launch_bounds__(512, 2)
gemm2_kernel(const float* __restrict__ Wg, const float* __restrict__ bg) {
    extern __shared__ float smem[];
    float* sWg  = smem;
    float* sagg = smem + 16384;
    __shared__ float sbg[128];

    int tid = threadIdx.x;
    for (int i = tid; i < 16384; i += 512) sWg[i] = Wg[i];
    if (tid < 128) sbg[tid] = bg[tid];
    __syncthreads();

    for (int t0 = blockIdx.x * 32; t0 < NN2; t0 += gridDim.x * 32) {
#pragma unroll
        for (int k = 0; k < 8; k++)
            sagg[tid + 512*k] = g_agg[(size_t)t0 * 128 + tid + 512*k];
        __syncthreads();

        int tg = tid >> 5;
        int q  = tid & 31;
        const float* a0p = &sagg[(2*tg + 0) * 128];
        const float* a1p = &sagg[(2*tg + 1) * 128];
        const float4* W4 = (const float4*)sWg;

        u64 acc[4];
#pragma unroll
        for (int j = 0; j < 4; j++) acc[j] = 0ull;
#pragma unroll 4
        for (int i = 0; i < 128; i++) {
            float4 w = W4[i * 32 + q];
            u64 wlo = pk2(w.x, w.y), whi = pk2(w.z, w.w);
            u64 x0 = pk1(a0p[i]), x1 = pk1(a1p[i]);
            acc[0] = ff2(x0, wlo, acc[0]); acc[1] = ff2(x0, whi, acc[1]);
            acc[2] = ff2(x1, wlo, acc[2]); acc[3] = ff2(x1, whi, acc[3]);
        }
        int o = 4 * q;
        u64 bb0 = pk2(sbg[o], sbg[o+1]), bb1 = pk2(sbg[o+2], sbg[o+3]);
#pragma unroll
        for (int tt = 0; tt < 2; tt++) {
            float2 v0 = upk(add2(acc[tt*2],   bb0));
            float2 v1 = upk(add2(acc[tt*2+1], bb1));
            float* op = &g_h2[(size_t)(t0 + 2*tg + tt) * 128 + o];
            op[0] = fmaxf(v0.x, 0.f);
            op[1] = fmaxf(v0.y, 0.f);
            op[2] = fmaxf(v1.x, 0.f);
            op[3] = fmaxf(v1.y, 0.f);
        }
        __syncthreads();
    }
}

// ---------------------------------------------------------------------------
// tail: T=16 targets/iter, thread=(pair8, q32, ihalf2), float4 weights,
// 2 targets per thread, shfl-xor(1) half-reduce. 512 threads, grid 296.
// ---------------------------------------------------------------------------
#define TAIL_DYN_FLOATS (128*128 + 64*128 + 16*128 + 16*64)

__global__ void __launch_bounds__(512, 2)
tail_kernel(const float* __restrict__ x,
            const int*   __restrict__ idx1,
            const int*   __restrict__ idx2,
            const float* __restrict__ Wup, const float* __restrict__ bup,
            const float* __restrict__ Wsc, const float* __restrict__ bsc,
            float* __restrict__ out) {
    extern __shared__ float smem[];
    float* sWup = smem;                       // 16384
    float* sWsc = smem + 16384;               // 8192
    float* sh2  = smem + 24576;               // 16*128
    float* sx   = smem + 24576 + 16*128;      // 16*64

    __shared__ float sbup[128], sbsc[128];

    int tid = threadIdx.x;
    for (int i = tid; i < 16384; i += 512) sWup[i] = Wup[i];
    for (int i = tid; i < 8192;  i += 512) sWsc[i] = Wsc[i];
    if (tid < 128) { sbup[tid] = bup[tid]; sbsc[tid] = bsc[tid]; }
    __syncthreads();

    const float4* Wu4 = (const float4*)sWup;
    const float4* Ws4 = (const float4*)sWsc;

    for (int t0 = blockIdx.x * 16; t0 < NN2; t0 += gridDim.x * 16) {
#pragma unroll
        for (int k = 0; k < 4; k++)
            sh2[tid + 512*k] = g_h2[(size_t)t0 * 128 + tid + 512*k];
        {
            int t = tid >> 5, f2 = tid & 31;
            int xr = idx1[idx2[t0 + t]];
            const float2* xp = (const float2*)&x[(size_t)xr * 64];
            ((float2*)&sx[t * 64])[f2] = xp[f2];
        }
        __syncthreads();

        int tg = tid >> 6;             // 8 pairs (2 targets each)
        int q  = (tid >> 1) & 31;      // 4 outputs
        int c  = tid & 1;              // i-half
        const float* h0 = &sh2[(2*tg + 0) * 128];
        const float* h1 = &sh2[(2*tg + 1) * 128];
        const float* x0 = &sx[(2*tg + 0) * 64];
        const float* x1 = &sx[(2*tg + 1) * 64];

        u64 ua[4], sa[4];
#pragma unroll
        for (int j = 0; j < 4; j++) { ua[j] = 0ull; sa[j] = 0ull; }
#pragma unroll 4
        for (int ii = 0; ii < 64; ii++) {
            int i = c * 64 + ii;
            float4 w = Wu4[i * 32 + q];
            u64 wlo = pk2(w.x, w.y), whi = pk2(w.z, w.w);
            u64 a0 = pk1(h0[i]), a1 = pk1(h1[i]);
            ua[0] = ff2(a0, wlo, ua[0]); ua[1] = ff2(a0, whi, ua[1]);
            ua[2] = ff2(a1, wlo, ua[2]); ua[3] = ff2(a1, whi, ua[3]);
        }
#pragma unroll 4
        for (int ii = 0; ii < 32; ii++) {
            int i = c * 32 + ii;
            float4 w = Ws4[i * 32 + q];
            u64 wlo = pk2(w.x, w.y), whi = pk2(w.z, w.w);
            u64 a0 = pk1(x0[i]), a1 = pk1(x1[i]);
            sa[0] = ff2(a0, wlo, sa[0]); sa[1] = ff2(a0, whi, sa[1]);
            sa[2] = ff2(a1, wlo, sa[2]); sa[3] = ff2(a1, whi, sa[3]);
        }
#pragma unroll
        for (int j = 0; j < 4; j++) {
            ua[j] = add2(ua[j], __shfl_xor_sync(0xFFFFFFFFu, ua[j], 1));
            sa[j] = add2(sa[j], __shfl_xor_sync(0xFFFFFFFFu, sa[j], 1));
        }
        if (c == 0) {
            int o = 4 * q;
            u64 bu0 = pk2(sbup[o], sbup[o+1]), bu1 = pk2(sbup[o+2], sbup[o+3]);
            u64 bs0 = pk2(sbsc[o], sbsc[o+1]), bs1 = pk2(sbsc[o+2], sbsc[o+3]);
#pragma unroll
            for (int tt = 0; tt < 2; tt++) {
                float2 a0 = upk(add2(ua[tt*2],   bu0));
                float2 a1 = upk(add2(ua[tt*2+1], bu1));
                float2 c0 = upk(add2(sa[tt*2],   bs0));
                float2 c1 = upk(add2(sa[tt*2+1], bs1));
                float* opt = &out[(size_t)(t0 + 2*tg + tt) * 128 + o];
                opt[0] = fmaxf(fmaxf(a0.x, 0.f) + fmaxf(c0.x, 0.f), 0.f);
                opt[1] = fmaxf(fmaxf(a0.y, 0.f) + fmaxf(c0.y, 0.f), 0.f);
                opt[2] = fmaxf(fmaxf(a1.x, 0.f) + fmaxf(c1.x, 0.f), 0.f);
                opt[3] = fmaxf(fmaxf(a1.y, 0.f) + fmaxf(c1.y, 0.f), 0.f);
            }
        }
        __syncthreads();
    }
}

// ---------------------------------------------------------------------------
extern "C" void kernel_launch(void* const* d_in, const int* in_sizes, int n_in,
                              void* d_out, int out_size) {
    const float* x      = (const float*)d_in[0];
    const float* pos    = (const float*)d_in[1];
    const float* W_down = (const float*)d_in[2];
    const float* b_down = (const float*)d_in[3];
    const float* W_pp1  = (const float*)d_in[4];
    const float* b_pp1  = (const float*)d_in[5];
    const float* W_att1 = (const float*)d_in[6];
    const float* b_att1 = (const float*)d_in[7];
    const float* W_g1   = (const float*)d_in[8];
    const float* b_g1   = (const float*)d_in[9];
    const float* W_pp2  = (const float*)d_in[10];
    const float* b_pp2  = (const float*)d_in[11];
    const float* W_att2 = (const float*)d_in[12];
    const float* b_att2 = (const float*)d_in[13];
    const float* W_g2   = (const float*)d_in[14];
    const float* b_g2   = (const float*)d_in[15];
    const float* W_up   = (const float*)d_in[16];
    const float* b_up   = (const float*)d_in[17];
    const float* W_sc   = (const float*)d_in[18];
    const float* b_sc   = (const float*)d_in[19];
    const int*   idx1   = (const int*)d_in[20];
    const int*   idx2   = (const int*)d_in[21];
    const int*   src1   = (const int*)d_in[22];
    const int*   src2   = (const int*)d_in[24];
    float* out = (float*)d_out;

    cudaFuncSetAttribute(conv1_kernel, cudaFuncAttributeMaxDynamicSharedMemorySize,
                         C1_DYN_FLOATS * (int)sizeof(float));
    cudaFuncSetAttribute(gemm_hw2_kernel, cudaFuncAttributeMaxDynamicSharedMemorySize,
                         GHW2_DYN_FLOATS * (int)sizeof(float));
    cudaFuncSetAttribute(conv2_kernel, cudaFuncAttributeMaxDynamicSharedMemorySize,
                         C2_DYN_FLOATS * (int)sizeof(float));
    cudaFuncSetAttribute(gemm2_kernel, cudaFuncAttributeMaxDynamicSharedMemorySize,
                         G2_DYN_FLOATS * (int)sizeof(float));
    cudaFuncSetAttribute(tail_kernel, cudaFuncAttributeMaxDynamicSharedMemorySize,
                         TAIL_DYN_FLOATS * (int)sizeof(float));

    down_kernel<<<128, 512>>>(x, W_down, b_down, W_att1);
    conv1_kernel<<<296, 512, C1_DYN_FLOATS * sizeof(float)>>>(
        pos, idx1, src1, W_pp1, b_pp1, W_att1, b_att1, W_g1, b_g1);
    gemm_hw2_kernel<<<296, 512, GHW2_DYN_FLOATS * sizeof(float)>>>(W_att2);
    conv2_kernel<<<296, 512, C2_DYN_FLOATS * sizeof(float)>>>(
        pos, idx1, idx2, src2, W_pp2, b_pp2, W_att2, b_att2);
    gemm2_kernel<<<296, 512, G2_DYN_FLOATS * sizeof(float)>>>(W_g2, b_g2);
    tail_kernel<<<296, 512, TAIL_DYN_FLOATS * sizeof(float)>>>(
        x, idx1, idx2, W_up, b_up, W_sc, b_sc, out);
}

// round 15
// speedup vs baseline: 1.0522x; 1.0161x over previous
#include <cuda_runtime.h>
#include <math.h>

#define NPTS 65536
#define NN1  16384
#define NN2  8192
#define KNN  16

typedef unsigned long long u64;

__device__ __forceinline__ u64 pk2(float lo, float hi) {
    u64 r; asm("mov.b64 %0,{%1,%2};" : "=l"(r) : "f"(lo), "f"(hi)); return r;
}
__device__ __forceinline__ u64 pk1(float v) { return pk2(v, v); }
__device__ __forceinline__ float2 upk(u64 v) {
    float2 f; asm("mov.b64 {%0,%1},%2;" : "=f"(f.x), "=f"(f.y) : "l"(v)); return f;
}
__device__ __forceinline__ u64 ff2(u64 a, u64 b, u64 c) {
    u64 d; asm("fma.rn.f32x2 %0,%1,%2,%3;" : "=l"(d) : "l"(a), "l"(b), "l"(c)); return d;
}
__device__ __forceinline__ u64 add2(u64 a, u64 b) {
    u64 d; asm("add.rn.f32x2 %0,%1,%2;" : "=l"(d) : "l"(a), "l"(b)); return d;
}

// Intermediate activations (device globals — no allocation allowed)
__device__ float g_h  [NPTS * 32];
__device__ float g_hW1[(size_t)NPTS * 64];    // h @ Watt1_top (rows 0..31)
__device__ float g_h1 [(size_t)NN1 * 64];
__device__ float g_hW2[(size_t)NN1 * 128];    // h1 @ Watt2_top (rows 0..63)
__device__ float g_agg[(size_t)NN2 * 128];
__device__ float g_h2 [(size_t)NN2 * 128];

// ---------------------------------------------------------------------------
// down: h = relu(x @ W_down + b_down); hW1 = h @ Watt1_top (no bias/relu)
// ---------------------------------------------------------------------------
__global__ void __launch_bounds__(512)
down_kernel(const float* __restrict__ x,
            const float* __restrict__ W,
            const float* __restrict__ b,
            const float* __restrict__ Watt1) {
    __shared__ float sW[64 * 32];
    __shared__ float sWt[32 * 64];
    __shared__ float sb[32];
    int tid = threadIdx.x;
    for (int i = tid; i < 64 * 32; i += 512) { sW[i] = W[i]; sWt[i] = Watt1[i]; }
    if (tid < 32) sb[tid] = b[tid];
    __syncthreads();

    int p = blockIdx.x * 512 + tid;

    float xr[64];
    const float4* xp = (const float4*)(x + (size_t)p * 64);
#pragma unroll
    for (int i = 0; i < 16; i++) {
        float4 v = xp[i];
        xr[4*i+0] = v.x; xr[4*i+1] = v.y; xr[4*i+2] = v.z; xr[4*i+3] = v.w;
    }
    u64 acc[16];
#pragma unroll
    for (int j = 0; j < 16; j++) acc[j] = pk2(sb[2*j], sb[2*j+1]);
#pragma unroll 4
    for (int i = 0; i < 64; i++) {
        u64 xi = pk1(xr[i]);
        const u64* wr = (const u64*)&sW[i * 32];
#pragma unroll
        for (int j = 0; j < 16; j++) acc[j] = ff2(xi, wr[j], acc[j]);
    }
    float h[32];
    float* op = &g_h[(size_t)p * 32];
#pragma unroll
    for (int j = 0; j < 16; j++) {
        float2 v = upk(acc[j]);
        h[2*j]   = fmaxf(v.x, 0.f);
        h[2*j+1] = fmaxf(v.y, 0.f);
        op[2*j]   = h[2*j];
        op[2*j+1] = h[2*j+1];
    }
    u64* wop = (u64*)&g_hW1[(size_t)p * 64];
#pragma unroll
    for (int half = 0; half < 2; half++) {
        u64 acc2[16];
#pragma unroll
        for (int j = 0; j < 16; j++) acc2[j] = 0ull;
#pragma unroll 4
        for (int i = 0; i < 32; i++) {
            u64 xi = pk1(h[i]);
            const u64* wr = (const u64*)&sWt[i * 64 + half * 32];
#pragma unroll
            for (int j = 0; j < 16; j++) acc2[j] = ff2(xi, wr[j], acc2[j]);
        }
#pragma unroll
        for (int j = 0; j < 16; j++) wop[half * 16 + j] = acc2[j];
    }
}

// ---------------------------------------------------------------------------
// conv1: T=8 targets/iter, 512 threads, grid 296, occ 2.
// Gather pp MLP vectorized (u64 weight pairs). att deferred-LDG init.
// ---------------------------------------------------------------------------
#define FT1  20
#define FT1A 18
#define SH1S 36
#define C1_DYN_FLOATS (320 + 2048 + 4096 + 8*32*FT1 + 8*64*FT1A + 8*16*SH1S)

__global__ void __launch_bounds__(512, 2)
conv1_kernel(const float* __restrict__ pos,
             const int*   __restrict__ idx1,
             const int*   __restrict__ src1,
             const float* __restrict__ Wpp, const float* __restrict__ bpp,
             const float* __restrict__ Watt, const float* __restrict__ batt,
             const float* __restrict__ Wg,  const float* __restrict__ bg) {
    extern __shared__ float smem[];
    float* sWpp  = smem;                        // 320
    float* sWattB= smem + 320;                  // 2048 (Watt rows 32..63)
    float* sWg   = smem + 2368;                 // 4096
    float* fijT  = smem + 6464;                 // 8*32*20 [t][rij feat][edge]
    float* attT  = smem + 6464 + 8*32*FT1;      // 8*64*18 [t][o][edge]
    float* sh    = smem + 6464 + 8*32*FT1 + 8*64*FT1A;  // 8*16*36 [et][feat]

    __shared__ __align__(8) float sbpp[32];
    __shared__ float sbatt[64], sbg[64];
    __shared__ float sv[128];
    __shared__ float aggS[8][64];
    __shared__ int   ssrc[128];

    int tid = threadIdx.x;
    for (int i = tid; i < 320; i += 512) sWpp[i] = Wpp[i];
    for (int i = tid; i < 2048; i += 512) sWattB[i] = Watt[32*64 + i];
    for (int i = tid; i < 4096; i += 512) sWg[i] = Wg[i];
    if (tid < 32) sbpp[tid] = bpp[tid];
    if (tid < 64) { sbatt[tid] = batt[tid]; sbg[tid] = bg[tid]; }
    __syncthreads();

    for (int t0 = blockIdx.x * 8; t0 < NN1; t0 += gridDim.x * 8) {
        // ---- gather: e fastest; h row-major + rij (vectorized); record src ----
        {
            int e   = tid & 15;
            int r   = tid >> 4;      // 0..31
            int t   = r >> 2;        // 0..7
            int sub = r & 3;         // 0..3
            int et  = t * 16 + e;
            int tgt = t0 + t;
            int pi = idx1[tgt];
            float pix = pos[pi*3+0], piy = pos[pi*3+1], piz = pos[pi*3+2];
            int s = src1[tgt * KNN + e];
            if (sub == 0) ssrc[et] = s;
            float pjx = pos[s*3+0], pjy = pos[s*3+1], pjz = pos[s*3+2];
            float vx = pix - pjx, vy = piy - pjy, vz = piz - pjz;
            float rel[10];
            rel[0] = pix; rel[1] = piy; rel[2] = piz;
            rel[3] = pjx; rel[4] = pjy; rel[5] = pjz;
            rel[6] = vx;  rel[7] = vy;  rel[8] = vz;
            rel[9] = sqrtf(vx*vx + vy*vy + vz*vz);

            const float4* hp = (const float4*)&g_h[(size_t)s * 32 + sub * 8];
            float4* shp = (float4*)&sh[et * SH1S + sub * 8];
            shp[0] = hp[0]; shp[1] = hp[1];

            u64 pa[4];
            const u64* bp = (const u64*)&sbpp[sub * 8];
#pragma unroll
            for (int j = 0; j < 4; j++) pa[j] = bp[j];
#pragma unroll
            for (int i = 0; i < 10; i++) {
                u64 xi = pk1(rel[i]);
                const u64* wr = (const u64*)&sWpp[i * 32 + sub * 8];
#pragma unroll
                for (int j = 0; j < 4; j++) pa[j] = ff2(xi, wr[j], pa[j]);
            }
            float* fd = &fijT[(t * 32 + sub * 8) * FT1 + e];
#pragma unroll
            for (int j = 0; j < 4; j++) {
                float2 v = upk(pa[j]);
                fd[(2*j)   * FT1] = fmaxf(v.x, 0.f);
                fd[(2*j+1) * FT1] = fmaxf(v.y, 0.f);
            }
        }
        __syncthreads();

        // ---- att: LDG issued first, FFMA loop, hW added after (hidden) ----
        {
            int t = tid >> 6;
            int q = (tid >> 2) & 15;
            int g = tid & 3;
            int eb = t * 16 + 4 * g;
            int s0 = ssrc[eb], s1 = ssrc[eb+1], s2 = ssrc[eb+2], s3 = ssrc[eb+3];
            float4 v0 = *(const float4*)&g_hW1[(size_t)s0 * 64 + 4*q];
            float4 v1 = *(const float4*)&g_hW1[(size_t)s1 * 64 + 4*q];
            float4 v2 = *(const float4*)&g_hW1[(size_t)s2 * 64 + 4*q];
            float4 v3 = *(const float4*)&g_hW1[(size_t)s3 * 64 + 4*q];

            u64 acc[8];
#pragma unroll
            for (int j = 0; j < 8; j++) acc[j] = 0ull;
            const float4* W4 = (const float4*)sWattB;
            const float* fb = &fijT[(t * 32) * FT1 + 4 * g];
#pragma unroll 4
            for (int i = 0; i < 32; i++) {
                float4 w = W4[i * 16 + q];
                u64 w0 = pk1(w.x), w1 = pk1(w.y), w2 = pk1(w.z), w3 = pk1(w.w);
                ulonglong2 a = *(const ulonglong2*)(fb + i * FT1);
                acc[0] = ff2(a.x, w0, acc[0]); acc[1] = ff2(a.y, w0, acc[1]);
                acc[2] = ff2(a.x, w1, acc[2]); acc[3] = ff2(a.y, w1, acc[3]);
                acc[4] = ff2(a.x, w2, acc[4]); acc[5] = ff2(a.y, w2, acc[5]);
                acc[6] = ff2(a.x, w3, acc[6]); acc[7] = ff2(a.y, w3, acc[7]);
            }
            acc[0] = add2(acc[0], pk2(v0.x, v1.x)); acc[1] = add2(acc[1], pk2(v2.x, v3.x));
            acc[2] = add2(acc[2], pk2(v0.y, v1.y)); acc[3] = add2(acc[3], pk2(v2.y, v3.y));
            acc[4] = add2(acc[4], pk2(v0.z, v1.z)); acc[5] = add2(acc[5], pk2(v2.z, v3.z));
            acc[6] = add2(acc[6], pk2(v0.w, v1.w)); acc[7] = add2(acc[7], pk2(v2.w, v3.w));
            float* ab = &attT[(t * 64 + 4 * q) * FT1A + 4 * g];
#pragma unroll
            for (int j = 0; j < 4; j++) {
                u64 bb = pk1(sbatt[4*q + j]);
                float2 r0 = upk(add2(acc[j*2],   bb));
                float2 r1 = upk(add2(acc[j*2+1], bb));
                *(u64*)&ab[j*FT1A + 0] = pk2(fmaxf(r0.x, 0.f), fmaxf(r0.y, 0.f));
                *(u64*)&ab[j*FT1A + 2] = pk2(fmaxf(r1.x, 0.f), fmaxf(r1.y, 0.f));
            }
        }
        __syncthreads();

        // ---- softmax per edge: single pass, no max; exp stored in place ----
        {
            int et = tid >> 2, c = tid & 3;
            float* ac = &attT[((et >> 4) * 64) * FT1A + (et & 15)];
            float s = 0.f;
#pragma unroll 4
            for (int k = 0; k < 16; k++) {
                float ev = __expf(ac[(c + 4*k)*FT1A]);
                s += ev;
                ac[(c + 4*k)*FT1A] = ev;
            }
            s += __shfl_xor_sync(0xFFFFFFFFu, s, 1);
            s += __shfl_xor_sync(0xFFFFFFFFu, s, 2);
            if (c == 0) sv[et] = 1.f / s;
        }
        __syncthreads();

        // ---- agg[o] = sum_e (ev * inv_sum) * fij ----
        {
            int t = tid >> 6, o = tid & 63;
            const float* ar = &attT[(t * 64 + o) * FT1A];
            float a = 0.f;
            if (o < 32) {
                const float* hb = &sh[(t * 16) * SH1S + o];
#pragma unroll
                for (int e = 0; e < 16; e++)
                    a += ar[e] * sv[t * 16 + e] * hb[e * SH1S];
            } else {
                const float* fr = &fijT[(t * 32 + (o - 32)) * FT1];
#pragma unroll
                for (int e = 0; e < 16; e++)
                    a += ar[e] * sv[t * 16 + e] * fr[e];
            }
            aggS[t][o] = a;
        }
        __syncthreads();

        // ---- global: h1 = relu(agg @ Wg + bg): (t8, op32, c2), shfl ----
        {
            int t = tid >> 6, op = (tid >> 1) & 31, c = tid & 1;
            u64 acc = 0ull;
#pragma unroll 4
            for (int ii = 0; ii < 32; ii++) {
                int i = c * 32 + ii;
                acc = ff2(pk1(aggS[t][i]), *(const u64*)&sWg[i*64 + 2*op], acc);
            }
            u64 other = __shfl_xor_sync(0xFFFFFFFFu, acc, 1);
            acc = add2(acc, other);
            if (c == 0) {
                float2 v = upk(acc);
                int o = 2 * op;
                float* opt = &g_h1[(size_t)(t0 + t) * 64 + o];
                opt[0] = fmaxf(v.x + sbg[o],   0.f);
                opt[1] = fmaxf(v.y + sbg[o+1], 0.f);
            }
        }
        __syncthreads();
    }
}

// ---------------------------------------------------------------------------
// gemm_hw2: g_hW2 = g_h1 @ Watt2_top  [16384,64]@[64,128]
// ---------------------------------------------------------------------------
#define GHW2_DYN_FLOATS (64*128 + 32*64)

__global__ void __launch_bounds__(512, 2)
gemm_hw2_kernel(const float* __restrict__ Watt2) {
    extern __shared__ float smem[];
    float* sW   = smem;
    float* sact = smem + 64*128;

    int tid = threadIdx.x;
    for (int i = tid; i < 64*128; i += 512) sW[i] = Watt2[i];
    __syncthreads();

    for (int t0 = blockIdx.x * 32; t0 < NN1; t0 += gridDim.x * 32) {
        ((float4*)sact)[tid] = ((const float4*)&g_h1[(size_t)t0 * 64])[tid];
        __syncthreads();

        int tg = tid >> 5;
        int q  = tid & 31;
        const float* a0p = &sact[(2*tg + 0) * 64];
        const float* a1p = &sact[(2*tg + 1) * 64];
        const float4* W4 = (const float4*)sW;

        u64 acc[4];
#pragma unroll
        for (int j = 0; j < 4; j++) acc[j] = 0ull;
#pragma unroll 4
        for (int i = 0; i < 64; i++) {
            float4 w = W4[i * 32 + q];
            u64 wlo = pk2(w.x, w.y), whi = pk2(w.z, w.w);
            u64 x0 = pk1(a0p[i]), x1 = pk1(a1p[i]);
            acc[0] = ff2(x0, wlo, acc[0]); acc[1] = ff2(x0, whi, acc[1]);
            acc[2] = ff2(x1, wlo, acc[2]); acc[3] = ff2(x1, whi, acc[3]);
        }
        int o = 4 * q;
        u64* o0 = (u64*)&g_hW2[(size_t)(t0 + 2*tg) * 128 + o];
        u64* o1 = (u64*)&g_hW2[(size_t)(t0 + 2*tg + 1) * 128 + o];
        o0[0] = acc[0]; o0[1] = acc[1];
        o1[0] = acc[2]; o1[1] = acc[3];
        __syncthreads();
    }
}

// ---------------------------------------------------------------------------
// conv2: T=4 targets/iter, 512 threads, grid 296, occ 2.
// Gather pp MLP vectorized (u64 weight pairs). att deferred-LDG init.
// ---------------------------------------------------------------------------
#define FT2   20
#define FT2A  18
#define SH2S  68
#define C2_DYN_FLOATS (640 + 8192 + 4*64*FT2 + 4*128*FT2A + 4*16*SH2S)

__global__ void __launch_bounds__(512, 2)
conv2_kernel(const float* __restrict__ pos,
             const int*   __restrict__ idx1,
             const int*   __restrict__ idx2,
             const int*   __restrict__ src2,
             const float* __restrict__ Wpp, const float* __restrict__ bpp,
             const float* __restrict__ Watt, const float* __restrict__ batt) {
    extern __shared__ float smem[];
    float* sWpp  = smem;                                // 640
    float* sWattB= smem + 640;                          // 8192 (rows 64..127)
    float* fijT  = smem + 640 + 8192;                   // 4*64*20
    float* attT  = smem + 640 + 8192 + 4*64*FT2;        // 4*128*18
    float* sh1   = smem + 640 + 8192 + 4*64*FT2 + 4*128*FT2A;  // 4*16*68

    __shared__ __align__(8) float sbpp[64];
    __shared__ float sbatt[128];
    __shared__ float sv[64];
    __shared__ int   ssrc[64];

    int tid = threadIdx.x;
    for (int i = tid; i < 640; i += 512) sWpp[i] = Wpp[i];
    for (int i = tid; i < 8192; i += 512) sWattB[i] = Watt[64*128 + i];
    if (tid < 64)  sbpp[tid] = bpp[tid];
    if (tid < 128) sbatt[tid] = batt[tid];
    __syncthreads();

    for (int t0 = blockIdx.x * 4; t0 < NN2; t0 += gridDim.x * 4) {
        // ---- gather: e fastest; h1 row-major + rij (vectorized); record src ----
        {
            int e   = tid & 15;
            int idx = tid >> 4;      // 0..31
            int t   = idx >> 3;      // 0..3
            int sub = idx & 7;       // 0..7
            int et  = t * 16 + e;
            int tgt = t0 + t;
            int pidx = idx1[idx2[tgt]];
            float pix = pos[pidx*3+0], piy = pos[pidx*3+1], piz = pos[pidx*3+2];
            int s = src2[tgt * KNN + e];
            if (sub == 0) ssrc[et] = s;
            int pj = idx1[s];
            float pjx = pos[pj*3+0], pjy = pos[pj*3+1], pjz = pos[pj*3+2];
            float vx = pix - pjx, vy = piy - pjy, vz = piz - pjz;
            float rel[10];
            rel[0] = pix; rel[1] = piy; rel[2] = piz;
            rel[3] = pjx; rel[4] = pjy; rel[5] = pjz;
            rel[6] = vx;  rel[7] = vy;  rel[8] = vz;
            rel[9] = sqrtf(vx*vx + vy*vy + vz*vz);

            const float4* hp = (const float4*)&g_h1[(size_t)s * 64 + sub * 8];
            float4* shp = (float4*)&sh1[et * SH2S + sub * 8];
            shp[0] = hp[0]; shp[1] = hp[1];

            u64 pa[4];
            const u64* bp = (const u64*)&sbpp[sub * 8];
#pragma unroll
            for (int j = 0; j < 4; j++) pa[j] = bp[j];
#pragma unroll
            for (int i = 0; i < 10; i++) {
                u64 xi = pk1(rel[i]);
                const u64* wr = (const u64*)&sWpp[i * 64 + sub * 8];
#pragma unroll
                for (int j = 0; j < 4; j++) pa[j] = ff2(xi, wr[j], pa[j]);
            }
            float* fd = &fijT[(t * 64 + sub * 8) * FT2 + e];
#pragma unroll
            for (int j = 0; j < 4; j++) {
                float2 v = upk(pa[j]);
                fd[(2*j)   * FT2] = fmaxf(v.x, 0.f);
                fd[(2*j+1) * FT2] = fmaxf(v.y, 0.f);
            }
        }
        __syncthreads();

        // ---- att: LDG issued first, FFMA loop, hW added after (hidden) ----
        {
            int g  = tid & 3;
            int ql = (tid >> 2) & 7;
            int t  = (tid >> 5) & 3;
            int qh = tid >> 7;           // 0..3
            int q  = ql + 8 * qh;        // 0..31
            int eb = t * 16 + 4 * g;
            int s0 = ssrc[eb], s1 = ssrc[eb+1], s2 = ssrc[eb+2], s3 = ssrc[eb+3];
            float4 v0 = *(const float4*)&g_hW2[(size_t)s0 * 128 + 4*q];
            float4 v1 = *(const float4*)&g_hW2[(size_t)s1 * 128 + 4*q];
            float4 v2 = *(const float4*)&g_hW2[(size_t)s2 * 128 + 4*q];
            float4 v3 = *(const float4*)&g_hW2[(size_t)s3 * 128 + 4*q];

            u64 acc[8];
#pragma unroll
            for (int j = 0; j < 8; j++) acc[j] = 0ull;
            const float4* W4 = (const float4*)sWattB;
            const float* fb = &fijT[(t * 64) * FT2 + 4 * g];
#pragma unroll 4
            for (int i = 0; i < 64; i++) {
                float4 w = W4[i * 32 + q];
                u64 w0 = pk1(w.x), w1 = pk1(w.y), w2 = pk1(w.z), w3 = pk1(w.w);
                ulonglong2 a = *(const ulonglong2*)(fb + i * FT2);
                acc[0] = ff2(a.x, w0, acc[0]); acc[1] = ff2(a.y, w0, acc[1]);
                acc[2] = ff2(a.x, w1, acc[2]); acc[3] = ff2(a.y, w1, acc[3]);
                acc[4] = ff2(a.x, w2, acc[4]); acc[5] = ff2(a.y, w2, acc[5]);
                acc[6] = ff2(a.x, w3, acc[6]); acc[7] = ff2(a.y, w3, acc[7]);
            }
            acc[0] = add2(acc[0], pk2(v0.x, v1.x)); acc[1] = add2(acc[1], pk2(v2.x, v3.x));
            acc[2] = add2(acc[2], pk2(v0.y, v1.y)); acc[3] = add2(acc[3], pk2(v2.y, v3.y));
            acc[4] = add2(acc[4], pk2(v0.z, v1.z)); acc[5] = add2(acc[5], pk2(v2.z, v3.z));
            acc[6] = add2(acc[6], pk2(v0.w, v1.w)); acc[7] = add2(acc[7], pk2(v2.w, v3.w));
            float* ab = &attT[(t * 128 + 4 * q) * FT2A + 4 * g];
#pragma unroll
            for (int j = 0; j < 4; j++) {
                u64 bb = pk1(sbatt[4*q + j]);
                float2 r0 = upk(add2(acc[j*2],   bb));
                float2 r1 = upk(add2(acc[j*2+1], bb));
                *(u64*)&ab[j*FT2A + 0] = pk2(fmaxf(r0.x, 0.f), fmaxf(r0.y, 0.f));
                *(u64*)&ab[j*FT2A + 2] = pk2(fmaxf(r1.x, 0.f), fmaxf(r1.y, 0.f));
            }
        }
        __syncthreads();

        // ---- softmax per edge: single pass, no max; exp stored in place ----
        {
            int et = tid >> 3, cc = tid & 7;
            float* ac = &attT[((et >> 4) * 128) * FT2A + (et & 15)];
            float s = 0.f;
#pragma unroll 4
            for (int k = 0; k < 16; k++) {
                float ev = __expf(ac[(cc + 8*k)*FT2A]);
                s += ev;
                ac[(cc + 8*k)*FT2A] = ev;
            }
            s += __shfl_xor_sync(0xFFFFFFFFu, s, 1);
            s += __shfl_xor_sync(0xFFFFFFFFu, s, 2);
            s += __shfl_xor_sync(0xFFFFFFFFu, s, 4);
            if (cc == 0) sv[et] = 1.f / s;
        }
        __syncthreads();

        // ---- agg -> global scratch ----
        {
            int t = tid >> 7, o = tid & 127;
            const float* ar = &attT[(t * 128 + o) * FT2A];
            float a = 0.f;
            if (o < 64) {
                const float* hb = &sh1[(t * 16) * SH2S + o];
#pragma unroll
                for (int e = 0; e < 16; e++)
                    a += ar[e] * sv[t * 16 + e] * hb[e * SH2S];
            } else {
                const float* fr = &fijT[(t * 64 + (o - 64)) * FT2];
#pragma unroll
                for (int e = 0; e < 16; e++)
                    a += ar[e] * sv[t * 16 + e] * fr[e];
            }
            g_agg[(size_t)(t0 + t) * 128 + o] = a;
        }
        __syncthreads();
    }
}

// ---------------------------------------------------------------------------
// gemm2: h2 = relu(g_agg @ Wg + bg). T=32, thread=(tg16,q32)x2 targets.
// ---------------------------------------------------------------------------
#define G2_DYN_FLOATS (128*128 + 32*128)

__global__ void __launch_bounds__(512, 2)
gemm2_kernel(const float* __restrict__ Wg, const float* __restrict__ bg) {
    extern __shared__ float smem[];
    float* sWg  = smem;
    float* sagg = smem + 16384;
    __shared__ float sbg[128];

    int tid = threadIdx.x;
    for (int i = tid; i < 16384; i += 512) sWg[i] = Wg[i];
    if (tid < 128) sbg[tid] = bg[tid];
    __syncthreads();

    for (int t0 = blockIdx.x * 32; t0 < NN2; t0 += gridDim.x * 32) {
#pragma unroll
        for (int k = 0; k < 8; k++)
            sagg[tid + 512*k] = g_agg[(size_t)t0 * 128 + tid + 512*k];
        __syncthreads();

        int tg = tid >> 5;
        int q  = tid & 31;
        const float* a0p = &sagg[(2*tg + 0) * 128];
        const float* a1p = &sagg[(2*tg + 1) * 128];
        const float4* W4 = (const float4*)sWg;

        u64 acc[4];
#pragma unroll
        for (int j = 0; j < 4; j++) acc[j] = 0ull;
#pragma unroll 4
        for (int i = 0; i < 128; i++) {
            float4 w = W4[i * 32 + q];
            u64 wlo = pk2(w.x, w.y), whi = pk2(w.z, w.w);
            u64 x0 = pk1(a0p[i]), x1 = pk1(a1p[i]);
            acc[0] = ff2(x0, wlo, acc[0]); acc[1] = ff2(x0, whi, acc[1]);
            acc[2] = ff2(x1, wlo, acc[2]); acc[3] = ff2(x1, whi, acc[3]);
        }
        int o = 4 * q;
        u64 bb0 = pk2(sbg[o], sbg[o+1]), bb1 = pk2(sbg[o+2], sbg[o+3]);
#pragma unroll
        for (int tt = 0; tt < 2; tt++) {
            float2 v0 = upk(add2(acc[tt*2],   bb0));
            float2 v1 = upk(add2(acc[tt*2+1], bb1));
            float* op = &g_h2[(size_t)(t0 + 2*tg + tt) * 128 + o];
            op[0] = fmaxf(v0.x, 0.f);
            op[1] = fmaxf(v0.y, 0.f);
            op[2] = fmaxf(v1.x, 0.f);
            op[3] = fmaxf(v1.y, 0.f);
        }
        __syncthreads();
    }
}

// ---------------------------------------------------------------------------
// tail: T=16 targets/iter, thread=(pair8, q32, ihalf2), float4 weights,
// 2 targets per thread, shfl-xor(1) half-reduce. 512 threads, grid 296.
// ---------------------------------------------------------------------------
#define TAIL_DYN_FLOATS (128*128 + 64*128 + 16*128 + 16*64)

__global__ void __launch_bounds__(512, 2)
tail_kernel(const float* __restrict__ x,
            const int*   __restrict__ idx1,
            const int*   __restrict__ idx2,
            const float* __restrict__ Wup, const float* __restrict__ bup,
            const float* __restrict__ Wsc, const float* __restrict__ bsc,
            float* __restrict__ out) {
    extern __shared__ float smem[];
    float* sWup = smem;                       // 16384
    float* sWsc = smem + 16384;               // 8192
    float* sh2  = smem + 24576;               // 16*128
    float* sx   = smem + 24576 + 16*128;      // 16*64

    __shared__ float sbup[128], sbsc[128];

    int tid = threadIdx.x;
    for (int i = tid; i < 16384; i += 512) sWup[i] = Wup[i];
    for (int i = tid; i < 8192;  i += 512) sWsc[i] = Wsc[i];
    if (tid < 128) { sbup[tid] = bup[tid]; sbsc[tid] = bsc[tid]; }
    __syncthreads();

    const float4* Wu4 = (const float4*)sWup;
    const float4* Ws4 = (const float4*)sWsc;

    for (int t0 = blockIdx.x * 16; t0 < NN2; t0 += gridDim.x * 16) {
#pragma unroll
        for (int k = 0; k < 4; k++)
            sh2[tid + 512*k] = g_h2[(size_t)t0 * 128 + tid + 512*k];
        {
            int t = tid >> 5, f2 = tid & 31;
            int xr = idx1[idx2[t0 + t]];
            const float2* xp = (const float2*)&x[(size_t)xr * 64];
            ((float2*)&sx[t * 64])[f2] = xp[f2];
        }
        __syncthreads();

        int tg = tid >> 6;             // 8 pairs (2 targets each)
        int q  = (tid >> 1) & 31;      // 4 outputs
        int c  = tid & 1;              // i-half
        const float* h0 = &sh2[(2*tg + 0) * 128];
        const float* h1 = &sh2[(2*tg + 1) * 128];
        const float* x0 = &sx[(2*tg + 0) * 64];
        const float* x1 = &sx[(2*tg + 1) * 64];

        u64 ua[4], sa[4];
#pragma unroll
        for (int j = 0; j < 4; j++) { ua[j] = 0ull; sa[j] = 0ull; }
#pragma unroll 4
        for (int ii = 0; ii < 64; ii++) {
            int i = c * 64 + ii;
            float4 w = Wu4[i * 32 + q];
            u64 wlo = pk2(w.x, w.y), whi = pk2(w.z, w.w);
            u64 a0 = pk1(h0[i]), a1 = pk1(h1[i]);
            ua[0] = ff2(a0, wlo, ua[0]); ua[1] = ff2(a0, whi, ua[1]);
            ua[2] = ff2(a1, wlo, ua[2]); ua[3] = ff2(a1, whi, ua[3]);
        }
#pragma unroll 4
        for (int ii = 0; ii < 32; ii++) {
            int i = c * 32 + ii;
            float4 w = Ws4[i * 32 + q];
            u64 wlo = pk2(w.x, w.y), whi = pk2(w.z, w.w);
            u64 a0 = pk1(x0[i]), a1 = pk1(x1[i]);
            sa[0] = ff2(a0, wlo, sa[0]); sa[1] = ff2(a0, whi, sa[1]);
            sa[2] = ff2(a1, wlo, sa[2]); sa[3] = ff2(a1, whi, sa[3]);
        }
#pragma unroll
        for (int j = 0; j < 4; j++) {
            ua[j] = add2(ua[j], __shfl_xor_sync(0xFFFFFFFFu, ua[j], 1));
            sa[j] = add2(sa[j], __shfl_xor_sync(0xFFFFFFFFu, sa[j], 1));
        }
        if (c == 0) {
            int o = 4 * q;
            u64 bu0 = pk2(sbup[o], sbup[o+1]), bu1 = pk2(sbup[o+2], sbup[o+3]);
            u64 bs0 = pk2(sbsc[o], sbsc[o+1]), bs1 = pk2(sbsc[o+2], sbsc[o+3]);
#pragma unroll
            for (int tt = 0; tt < 2; tt++) {
                float2 a0 = upk(add2(ua[tt*2],   bu0));
                float2 a1 = upk(add2(ua[tt*2+1], bu1));
                float2 c0 = upk(add2(sa[tt*2],   bs0));
                float2 c1 = upk(add2(sa[tt*2+1], bs1));
                float* opt = &out[(size_t)(t0 + 2*tg + tt) * 128 + o];
                opt[0] = fmaxf(fmaxf(a0.x, 0.f) + fmaxf(c0.x, 0.f), 0.f);
                opt[1] = fmaxf(fmaxf(a0.y, 0.f) + fmaxf(c0.y, 0.f), 0.f);
                opt[2] = fmaxf(fmaxf(a1.x, 0.f) + fmaxf(c1.x, 0.f), 0.f);
                opt[3] = fmaxf(fmaxf(a1.y, 0.f) + fmaxf(c1.y, 0.f), 0.f);
            }
        }
        __syncthreads();
    }
}

// ---------------------------------------------------------------------------
extern "C" void kernel_launch(void* const* d_in, const int* in_sizes, int n_in,
                              void* d_out, int out_size) {
    const float* x      = (const float*)d_in[0];
    const float* pos    = (const float*)d_in[1];
    const float* W_down = (const float*)d_in[2];
    const float* b_down = (const float*)d_in[3];
    const float* W_pp1  = (const float*)d_in[4];
    const float* b_pp1  = (const float*)d_in[5];
    const float* W_att1 = (const float*)d_in[6];
    const float* b_att1 = (const float*)d_in[7];
    const float* W_g1   = (const float*)d_in[8];
    const float* b_g1   = (const float*)d_in[9];
    const float* W_pp2  = (const float*)d_in[10];
    const float* b_pp2  = (const float*)d_in[11];
    const float* W_att2 = (const float*)d_in[12];
    const float* b_att2 = (const float*)d_in[13];
    const float* W_g2   = (const float*)d_in[14];
    const float* b_g2   = (const float*)d_in[15];
    const float* W_up   = (const float*)d_in[16];
    const float* b_up   = (const float*)d_in[17];
    const float* W_sc   = (const float*)d_in[18];
    const float* b_sc   = (const float*)d_in[19];
    const int*   idx1   = (const int*)d_in[20];
    const int*   idx2   = (const int*)d_in[21];
    const int*   src1   = (const int*)d_in[22];
    const int*   src2   = (const int*)d_in[24];
    float* out = (float*)d_out;

    cudaFuncSetAttribute(conv1_kernel, cudaFuncAttributeMaxDynamicSharedMemorySize,
                         C1_DYN_FLOATS * (int)sizeof(float));
    cudaFuncSetAttribute(gemm_hw2_kernel, cudaFuncAttributeMaxDynamicSharedMemorySize,
                         GHW2_DYN_FLOATS * (int)sizeof(float));
    cudaFuncSetAttribute(conv2_kernel, cudaFuncAttributeMaxDynamicSharedMemorySize,
                         C2_DYN_FLOATS * (int)sizeof(float));
    cudaFuncSetAttribute(gemm2_kernel, cudaFuncAttributeMaxDynamicSharedMemorySize,
                         G2_DYN_FLOATS * (int)sizeof(float));
    cudaFuncSetAttribute(tail_kernel, cudaFuncAttributeMaxDynamicSharedMemorySize,
                         TAIL_DYN_FLOATS * (int)sizeof(float));

    down_kernel<<<128, 512>>>(x, W_down, b_down, W_att1);
    conv1_kernel<<<296, 512, C1_DYN_FLOATS * sizeof(float)>>>(
        pos, idx1, src1, W_pp1, b_pp1, W_att1, b_att1, W_g1, b_g1);
    gemm_hw2_kernel<<<296, 512, GHW2_DYN_FLOATS * sizeof(float)>>>(W_att2);
    conv2_kernel<<<296, 512, C2_DYN_FLOATS * sizeof(float)>>>(
        pos, idx1, idx2, src2, W_pp2, b_pp2, W_att2, b_att2);
    gemm2_kernel<<<296, 512, G2_DYN_FLOATS * sizeof(float)>>>(W_g2, b_g2);
    tail_kernel<<<296, 512, TAIL_DYN_FLOATS * sizeof(float)>>>(
        x, idx1, idx2, W_up, b_up, W_sc, b_sc, out);
}

// round 16
// speedup vs baseline: 1.0527x; 1.0005x over previous
#include <cuda_runtime.h>
#include <math.h>

#define NPTS 65536
#define NN1  16384
#define NN2  8192
#define KNN  16

typedef unsigned long long u64;

__device__ __forceinline__ u64 pk2(float lo, float hi) {
    u64 r; asm("mov.b64 %0,{%1,%2};" : "=l"(r) : "f"(lo), "f"(hi)); return r;
}
__device__ __forceinline__ u64 pk1(float v) { return pk2(v, v); }
__device__ __forceinline__ float2 upk(u64 v) {
    float2 f; asm("mov.b64 {%0,%1},%2;" : "=f"(f.x), "=f"(f.y) : "l"(v)); return f;
}
__device__ __forceinline__ u64 ff2(u64 a, u64 b, u64 c) {
    u64 d; asm("fma.rn.f32x2 %0,%1,%2,%3;" : "=l"(d) : "l"(a), "l"(b), "l"(c)); return d;
}
__device__ __forceinline__ u64 add2(u64 a, u64 b) {
    u64 d; asm("add.rn.f32x2 %0,%1,%2;" : "=l"(d) : "l"(a), "l"(b)); return d;
}
__device__ __forceinline__ u64 mul2(u64 a, u64 b) {
    u64 d; asm("mul.rn.f32x2 %0,%1,%2;" : "=l"(d) : "l"(a), "l"(b)); return d;
}

// Intermediate activations (device globals — no allocation allowed)
__device__ float g_h  [NPTS * 32];
__device__ float g_hW1[(size_t)NPTS * 64];    // h @ Watt1_top (rows 0..31)
__device__ float g_h1 [(size_t)NN1 * 64];
__device__ float g_hW2[(size_t)NN1 * 128];    // h1 @ Watt2_top (rows 0..63)
__device__ float g_agg[(size_t)NN2 * 128];
__device__ float g_h2 [(size_t)NN2 * 128];

// ---------------------------------------------------------------------------
// down: h = relu(x @ W_down + b_down); hW1 = h @ Watt1_top (no bias/relu)
// ---------------------------------------------------------------------------
__global__ void __launch_bounds__(512)
down_kernel(const float* __restrict__ x,
            const float* __restrict__ W,
            const float* __restrict__ b,
            const float* __restrict__ Watt1) {
    __shared__ float sW[64 * 32];
    __shared__ float sWt[32 * 64];
    __shared__ float sb[32];
    int tid = threadIdx.x;
    for (int i = tid; i < 64 * 32; i += 512) { sW[i] = W[i]; sWt[i] = Watt1[i]; }
    if (tid < 32) sb[tid] = b[tid];
    __syncthreads();

    int p = blockIdx.x * 512 + tid;

    float xr[64];
    const float4* xp = (const float4*)(x + (size_t)p * 64);
#pragma unroll
    for (int i = 0; i < 16; i++) {
        float4 v = xp[i];
        xr[4*i+0] = v.x; xr[4*i+1] = v.y; xr[4*i+2] = v.z; xr[4*i+3] = v.w;
    }
    u64 acc[16];
#pragma unroll
    for (int j = 0; j < 16; j++) acc[j] = pk2(sb[2*j], sb[2*j+1]);
#pragma unroll 4
    for (int i = 0; i < 64; i++) {
        u64 xi = pk1(xr[i]);
        const u64* wr = (const u64*)&sW[i * 32];
#pragma unroll
        for (int j = 0; j < 16; j++) acc[j] = ff2(xi, wr[j], acc[j]);
    }
    float h[32];
    float* op = &g_h[(size_t)p * 32];
#pragma unroll
    for (int j = 0; j < 16; j++) {
        float2 v = upk(acc[j]);
        h[2*j]   = fmaxf(v.x, 0.f);
        h[2*j+1] = fmaxf(v.y, 0.f);
        op[2*j]   = h[2*j];
        op[2*j+1] = h[2*j+1];
    }
    u64* wop = (u64*)&g_hW1[(size_t)p * 64];
#pragma unroll
    for (int half = 0; half < 2; half++) {
        u64 acc2[16];
#pragma unroll
        for (int j = 0; j < 16; j++) acc2[j] = 0ull;
#pragma unroll 4
        for (int i = 0; i < 32; i++) {
            u64 xi = pk1(h[i]);
            const u64* wr = (const u64*)&sWt[i * 64 + half * 32];
#pragma unroll
            for (int j = 0; j < 16; j++) acc2[j] = ff2(xi, wr[j], acc2[j]);
        }
#pragma unroll
        for (int j = 0; j < 16; j++) wop[half * 16 + j] = acc2[j];
    }
}

// ---------------------------------------------------------------------------
// conv1: T=8 targets/iter, 512 threads, grid 296, occ 2.
// ---------------------------------------------------------------------------
#define FT1  20
#define FT1A 18
#define SH1S 36
#define C1_DYN_FLOATS (320 + 2048 + 4096 + 8*32*FT1 + 8*64*FT1A + 8*16*SH1S)

__global__ void __launch_bounds__(512, 2)
conv1_kernel(const float* __restrict__ pos,
             const int*   __restrict__ idx1,
             const int*   __restrict__ src1,
             const float* __restrict__ Wpp, const float* __restrict__ bpp,
             const float* __restrict__ Watt, const float* __restrict__ batt,
             const float* __restrict__ Wg,  const float* __restrict__ bg) {
    extern __shared__ float smem[];
    float* sWpp  = smem;                        // 320
    float* sWattB= smem + 320;                  // 2048 (Watt rows 32..63)
    float* sWg   = smem + 2368;                 // 4096
    float* fijT  = smem + 6464;                 // 8*32*20 [t][rij feat][edge]
    float* attT  = smem + 6464 + 8*32*FT1;      // 8*64*18 [t][o][edge]
    float* sh    = smem + 6464 + 8*32*FT1 + 8*64*FT1A;  // 8*16*36 [et][feat]

    __shared__ __align__(8) float sbpp[32];
    __shared__ float sbatt[64], sbg[64];
    __shared__ __align__(8) float sv[128];
    __shared__ float aggS[8][64];
    __shared__ int   ssrc[128];

    int tid = threadIdx.x;
    for (int i = tid; i < 320; i += 512) sWpp[i] = Wpp[i];
    for (int i = tid; i < 2048; i += 512) sWattB[i] = Watt[32*64 + i];
    for (int i = tid; i < 4096; i += 512) sWg[i] = Wg[i];
    if (tid < 32) sbpp[tid] = bpp[tid];
    if (tid < 64) { sbatt[tid] = batt[tid]; sbg[tid] = bg[tid]; }
    __syncthreads();

    for (int t0 = blockIdx.x * 8; t0 < NN1; t0 += gridDim.x * 8) {
        // ---- gather: e fastest; h row-major + rij (vectorized); record src ----
        {
            int e   = tid & 15;
            int r   = tid >> 4;
            int t   = r >> 2;
            int sub = r & 3;
            int et  = t * 16 + e;
            int tgt = t0 + t;
            int pi = idx1[tgt];
            float pix = pos[pi*3+0], piy = pos[pi*3+1], piz = pos[pi*3+2];
            int s = src1[tgt * KNN + e];
            if (sub == 0) ssrc[et] = s;
            float pjx = pos[s*3+0], pjy = pos[s*3+1], pjz = pos[s*3+2];
            float vx = pix - pjx, vy = piy - pjy, vz = piz - pjz;
            float rel[10];
            rel[0] = pix; rel[1] = piy; rel[2] = piz;
            rel[3] = pjx; rel[4] = pjy; rel[5] = pjz;
            rel[6] = vx;  rel[7] = vy;  rel[8] = vz;
            rel[9] = sqrtf(vx*vx + vy*vy + vz*vz);

            const float4* hp = (const float4*)&g_h[(size_t)s * 32 + sub * 8];
            float4* shp = (float4*)&sh[et * SH1S + sub * 8];
            shp[0] = hp[0]; shp[1] = hp[1];

            u64 pa[4];
            const u64* bp = (const u64*)&sbpp[sub * 8];
#pragma unroll
            for (int j = 0; j < 4; j++) pa[j] = bp[j];
#pragma unroll
            for (int i = 0; i < 10; i++) {
                u64 xi = pk1(rel[i]);
                const u64* wr = (const u64*)&sWpp[i * 32 + sub * 8];
#pragma unroll
                for (int j = 0; j < 4; j++) pa[j] = ff2(xi, wr[j], pa[j]);
            }
            float* fd = &fijT[(t * 32 + sub * 8) * FT1 + e];
#pragma unroll
            for (int j = 0; j < 4; j++) {
                float2 v = upk(pa[j]);
                fd[(2*j)   * FT1] = fmaxf(v.x, 0.f);
                fd[(2*j+1) * FT1] = fmaxf(v.y, 0.f);
            }
        }
        __syncthreads();

        // ---- att: LDG issued first, FFMA loop, hW added after (hidden) ----
        {
            int t = tid >> 6;
            int q = (tid >> 2) & 15;
            int g = tid & 3;
            int eb = t * 16 + 4 * g;
            int s0 = ssrc[eb], s1 = ssrc[eb+1], s2 = ssrc[eb+2], s3 = ssrc[eb+3];
            float4 v0 = *(const float4*)&g_hW1[(size_t)s0 * 64 + 4*q];
            float4 v1 = *(const float4*)&g_hW1[(size_t)s1 * 64 + 4*q];
            float4 v2 = *(const float4*)&g_hW1[(size_t)s2 * 64 + 4*q];
            float4 v3 = *(const float4*)&g_hW1[(size_t)s3 * 64 + 4*q];

            u64 acc[8];
#pragma unroll
            for (int j = 0; j < 8; j++) acc[j] = 0ull;
            const float4* W4 = (const float4*)sWattB;
            const float* fb = &fijT[(t * 32) * FT1 + 4 * g];
#pragma unroll 4
            for (int i = 0; i < 32; i++) {
                float4 w = W4[i * 16 + q];
                u64 w0 = pk1(w.x), w1 = pk1(w.y), w2 = pk1(w.z), w3 = pk1(w.w);
                ulonglong2 a = *(const ulonglong2*)(fb + i * FT1);
                acc[0] = ff2(a.x, w0, acc[0]); acc[1] = ff2(a.y, w0, acc[1]);
                acc[2] = ff2(a.x, w1, acc[2]); acc[3] = ff2(a.y, w1, acc[3]);
                acc[4] = ff2(a.x, w2, acc[4]); acc[5] = ff2(a.y, w2, acc[5]);
                acc[6] = ff2(a.x, w3, acc[6]); acc[7] = ff2(a.y, w3, acc[7]);
            }
            acc[0] = add2(acc[0], pk2(v0.x, v1.x)); acc[1] = add2(acc[1], pk2(v2.x, v3.x));
            acc[2] = add2(acc[2], pk2(v0.y, v1.y)); acc[3] = add2(acc[3], pk2(v2.y, v3.y));
            acc[4] = add2(acc[4], pk2(v0.z, v1.z)); acc[5] = add2(acc[5], pk2(v2.z, v3.z));
            acc[6] = add2(acc[6], pk2(v0.w, v1.w)); acc[7] = add2(acc[7], pk2(v2.w, v3.w));
            float* ab = &attT[(t * 64 + 4 * q) * FT1A + 4 * g];
#pragma unroll
            for (int j = 0; j < 4; j++) {
                u64 bb = pk1(sbatt[4*q + j]);
                float2 r0 = upk(add2(acc[j*2],   bb));
                float2 r1 = upk(add2(acc[j*2+1], bb));
                *(u64*)&ab[j*FT1A + 0] = pk2(fmaxf(r0.x, 0.f), fmaxf(r0.y, 0.f));
                *(u64*)&ab[j*FT1A + 2] = pk2(fmaxf(r1.x, 0.f), fmaxf(r1.y, 0.f));
            }
        }
        __syncthreads();

        // ---- softmax per edge: single pass, no max; exp stored in place ----
        {
            int et = tid >> 2, c = tid & 3;
            float* ac = &attT[((et >> 4) * 64) * FT1A + (et & 15)];
            float s = 0.f;
#pragma unroll 4
            for (int k = 0; k < 16; k++) {
                float ev = __expf(ac[(c + 4*k)*FT1A]);
                s += ev;
                ac[(c + 4*k)*FT1A] = ev;
            }
            s += __shfl_xor_sync(0xFFFFFFFFu, s, 1);
            s += __shfl_xor_sync(0xFFFFFFFFu, s, 2);
            if (c == 0) sv[et] = 1.f / s;
        }
        __syncthreads();

        // ---- agg[o] = sum_e (ev * inv_sum) * fij, edge-pair packed ----
        {
            int t = tid >> 6, o = tid & 63;
            const u64* ar2 = (const u64*)&attT[(t * 64 + o) * FT1A];
            const u64* sv2 = (const u64*)&sv[t * 16];
            u64 acc = 0ull;
            if (o < 32) {
                const float* hb = &sh[(t * 16) * SH1S + o];
#pragma unroll
                for (int e2 = 0; e2 < 8; e2++) {
                    u64 w = mul2(ar2[e2], sv2[e2]);
                    acc = ff2(w, pk2(hb[(2*e2)*SH1S], hb[(2*e2+1)*SH1S]), acc);
                }
            } else {
                const float4* fr = (const float4*)&fijT[(t * 32 + (o - 32)) * FT1];
#pragma unroll
                for (int k = 0; k < 4; k++) {
                    float4 f = fr[k];
                    acc = ff2(mul2(ar2[2*k],   sv2[2*k]),   pk2(f.x, f.y), acc);
                    acc = ff2(mul2(ar2[2*k+1], sv2[2*k+1]), pk2(f.z, f.w), acc);
                }
            }
            float2 v = upk(acc);
            aggS[t][o] = v.x + v.y;
        }
        __syncthreads();

        // ---- global: h1 = relu(agg @ Wg + bg): (t8, op32, c2), shfl ----
        {
            int t = tid >> 6, op = (tid >> 1) & 31, c = tid & 1;
            u64 acc = 0ull;
#pragma unroll 4
            for (int ii = 0; ii < 32; ii++) {
                int i = c * 32 + ii;
                acc = ff2(pk1(aggS[t][i]), *(const u64*)&sWg[i*64 + 2*op], acc);
            }
            u64 other = __shfl_xor_sync(0xFFFFFFFFu, acc, 1);
            acc = add2(acc, other);
            if (c == 0) {
                float2 v = upk(acc);
                int o = 2 * op;
                float* opt = &g_h1[(size_t)(t0 + t) * 64 + o];
                opt[0] = fmaxf(v.x + sbg[o],   0.f);
                opt[1] = fmaxf(v.y + sbg[o+1], 0.f);
            }
        }
        __syncthreads();
    }
}

// ---------------------------------------------------------------------------
// gemm_hw2: g_hW2 = g_h1 @ Watt2_top  [16384,64]@[64,128]
// ---------------------------------------------------------------------------
#define GHW2_DYN_FLOATS (64*128 + 32*64)

__global__ void __launch_bounds__(512, 2)
gemm_hw2_kernel(const float* __restrict__ Watt2) {
    extern __shared__ float smem[];
    float* sW   = smem;
    float* sact = smem + 64*128;

    int tid = threadIdx.x;
    for (int i = tid; i < 64*128; i += 512) sW[i] = Watt2[i];
    __syncthreads();

    for (int t0 = blockIdx.x * 32; t0 < NN1; t0 += gridDim.x * 32) {
        ((float4*)sact)[tid] = ((const float4*)&g_h1[(size_t)t0 * 64])[tid];
        __syncthreads();

        int tg = tid >> 5;
        int q  = tid & 31;
        const float* a0p = &sact[(2*tg + 0) * 64];
        const float* a1p = &sact[(2*tg + 1) * 64];
        const float4* W4 = (const float4*)sW;

        u64 acc[4];
#pragma unroll
        for (int j = 0; j < 4; j++) acc[j] = 0ull;
#pragma unroll 4
        for (int i = 0; i < 64; i++) {
            float4 w = W4[i * 32 + q];
            u64 wlo = pk2(w.x, w.y), whi = pk2(w.z, w.w);
            u64 x0 = pk1(a0p[i]), x1 = pk1(a1p[i]);
            acc[0] = ff2(x0, wlo, acc[0]); acc[1] = ff2(x0, whi, acc[1]);
            acc[2] = ff2(x1, wlo, acc[2]); acc[3] = ff2(x1, whi, acc[3]);
        }
        int o = 4 * q;
        u64* o0 = (u64*)&g_hW2[(size_t)(t0 + 2*tg) * 128 + o];
        u64* o1 = (u64*)&g_hW2[(size_t)(t0 + 2*tg + 1) * 128 + o];
        o0[0] = acc[0]; o0[1] = acc[1];
        o1[0] = acc[2]; o1[1] = acc[3];
        __syncthreads();
    }
}

// ---------------------------------------------------------------------------
// conv2: T=4 targets/iter, 512 threads, grid 296, occ 2.
// ---------------------------------------------------------------------------
#define FT2   20
#define FT2A  18
#define SH2S  68
#define C2_DYN_FLOATS (640 + 8192 + 4*64*FT2 + 4*128*FT2A + 4*16*SH2S)

__global__ void __launch_bounds__(512, 2)
conv2_kernel(const float* __restrict__ pos,
             const int*   __restrict__ idx1,
             const int*   __restrict__ idx2,
             const int*   __restrict__ src2,
             const float* __restrict__ Wpp, const float* __restrict__ bpp,
             const float* __restrict__ Watt, const float* __restrict__ batt) {
    extern __shared__ float smem[];
    float* sWpp  = smem;                                // 640
    float* sWattB= smem + 640;                          // 8192 (rows 64..127)
    float* fijT  = smem + 640 + 8192;                   // 4*64*20
    float* attT  = smem + 640 + 8192 + 4*64*FT2;        // 4*128*18
    float* sh1   = smem + 640 + 8192 + 4*64*FT2 + 4*128*FT2A;  // 4*16*68

    __shared__ __align__(8) float sbpp[64];
    __shared__ float sbatt[128];
    __shared__ __align__(8) float sv[64];
    __shared__ int   ssrc[64];

    int tid = threadIdx.x;
    for (int i = tid; i < 640; i += 512) sWpp[i] = Wpp[i];
    for (int i = tid; i < 8192; i += 512) sWattB[i] = Watt[64*128 + i];
    if (tid < 64)  sbpp[tid] = bpp[tid];
    if (tid < 128) sbatt[tid] = batt[tid];
    __syncthreads();

    for (int t0 = blockIdx.x * 4; t0 < NN2; t0 += gridDim.x * 4) {
        // ---- gather: e fastest; h1 row-major + rij (vectorized); record src ----
        {
            int e   = tid & 15;
            int idx = tid >> 4;
            int t   = idx >> 3;
            int sub = idx & 7;
            int et  = t * 16 + e;
            int tgt = t0 + t;
            int pidx = idx1[idx2[tgt]];
            float pix = pos[pidx*3+0], piy = pos[pidx*3+1], piz = pos[pidx*3+2];
            int s = src2[tgt * KNN + e];
            if (sub == 0) ssrc[et] = s;
            int pj = idx1[s];
            float pjx = pos[pj*3+0], pjy = pos[pj*3+1], pjz = pos[pj*3+2];
            float vx = pix - pjx, vy = piy - pjy, vz = piz - pjz;
            float rel[10];
            rel[0] = pix; rel[1] = piy; rel[2] = piz;
            rel[3] = pjx; rel[4] = pjy; rel[5] = pjz;
            rel[6] = vx;  rel[7] = vy;  rel[8] = vz;
            rel[9] = sqrtf(vx*vx + vy*vy + vz*vz);

            const float4* hp = (const float4*)&g_h1[(size_t)s * 64 + sub * 8];
            float4* shp = (float4*)&sh1[et * SH2S + sub * 8];
            shp[0] = hp[0]; shp[1] = hp[1];

            u64 pa[4];
            const u64* bp = (const u64*)&sbpp[sub * 8];
#pragma unroll
            for (int j = 0; j < 4; j++) pa[j] = bp[j];
#pragma unroll
            for (int i = 0; i < 10; i++) {
                u64 xi = pk1(rel[i]);
                const u64* wr = (const u64*)&sWpp[i * 64 + sub * 8];
#pragma unroll
                for (int j = 0; j < 4; j++) pa[j] = ff2(xi, wr[j], pa[j]);
            }
            float* fd = &fijT[(t * 64 + sub * 8) * FT2 + e];
#pragma unroll
            for (int j = 0; j < 4; j++) {
                float2 v = upk(pa[j]);
                fd[(2*j)   * FT2] = fmaxf(v.x, 0.f);
                fd[(2*j+1) * FT2] = fmaxf(v.y, 0.f);
            }
        }
        __syncthreads();

        // ---- att: LDG issued first, FFMA loop, hW added after (hidden) ----
        {
            int g  = tid & 3;
            int ql = (tid >> 2) & 7;
            int t  = (tid >> 5) & 3;
            int qh = tid >> 7;
            int q  = ql + 8 * qh;
            int eb = t * 16 + 4 * g;
            int s0 = ssrc[eb], s1 = ssrc[eb+1], s2 = ssrc[eb+2], s3 = ssrc[eb+3];
            float4 v0 = *(const float4*)&g_hW2[(size_t)s0 * 128 + 4*q];
            float4 v1 = *(const float4*)&g_hW2[(size_t)s1 * 128 + 4*q];
            float4 v2 = *(const float4*)&g_hW2[(size_t)s2 * 128 + 4*q];
            float4 v3 = *(const float4*)&g_hW2[(size_t)s3 * 128 + 4*q];

            u64 acc[8];
#pragma unroll
            for (int j = 0; j < 8; j++) acc[j] = 0ull;
            const float4* W4 = (const float4*)sWattB;
            const float* fb = &fijT[(t * 64) * FT2 + 4 * g];
#pragma unroll 4
            for (int i = 0; i < 64; i++) {
                float4 w = W4[i * 32 + q];
                u64 w0 = pk1(w.x), w1 = pk1(w.y), w2 = pk1(w.z), w3 = pk1(w.w);
                ulonglong2 a = *(const ulonglong2*)(fb + i * FT2);
                acc[0] = ff2(a.x, w0, acc[0]); acc[1] = ff2(a.y, w0, acc[1]);
                acc[2] = ff2(a.x, w1, acc[2]); acc[3] = ff2(a.y, w1, acc[3]);
                acc[4] = ff2(a.x, w2, acc[4]); acc[5] = ff2(a.y, w2, acc[5]);
                acc[6] = ff2(a.x, w3, acc[6]); acc[7] = ff2(a.y, w3, acc[7]);
            }
            acc[0] = add2(acc[0], pk2(v0.x, v1.x)); acc[1] = add2(acc[1], pk2(v2.x, v3.x));
            acc[2] = add2(acc[2], pk2(v0.y, v1.y)); acc[3] = add2(acc[3], pk2(v2.y, v3.y));
            acc[4] = add2(acc[4], pk2(v0.z, v1.z)); acc[5] = add2(acc[5], pk2(v2.z, v3.z));
            acc[6] = add2(acc[6], pk2(v0.w, v1.w)); acc[7] = add2(acc[7], pk2(v2.w, v3.w));
            float* ab = &attT[(t * 128 + 4 * q) * FT2A + 4 * g];
#pragma unroll
            for (int j = 0; j < 4; j++) {
                u64 bb = pk1(sbatt[4*q + j]);
                float2 r0 = upk(add2(acc[j*2],   bb));
                float2 r1 = upk(add2(acc[j*2+1], bb));
                *(u64*)&ab[j*FT2A + 0] = pk2(fmaxf(r0.x, 0.f), fmaxf(r0.y, 0.f));
                *(u64*)&ab[j*FT2A + 2] = pk2(fmaxf(r1.x, 0.f), fmaxf(r1.y, 0.f));
            }
        }
        __syncthreads();

        // ---- softmax per edge: single pass, no max; exp stored in place ----
        {
            int et = tid >> 3, cc = tid & 7;
            float* ac = &attT[((et >> 4) * 128) * FT2A + (et & 15)];
            float s = 0.f;
#pragma unroll 4
            for (int k = 0; k < 16; k++) {
                float ev = __expf(ac[(cc + 8*k)*FT2A]);
                s += ev;
                ac[(cc + 8*k)*FT2A] = ev;
            }
            s += __shfl_xor_sync(0xFFFFFFFFu, s, 1);
            s += __shfl_xor_sync(0xFFFFFFFFu, s, 2);
            s += __shfl_xor_sync(0xFFFFFFFFu, s, 4);
            if (cc == 0) sv[et] = 1.f / s;
        }
        __syncthreads();

        // ---- agg -> global scratch, edge-pair packed ----
        {
            int t = tid >> 7, o = tid & 127;
            const u64* ar2 = (const u64*)&attT[(t * 128 + o) * FT2A];
            const u64* sv2 = (const u64*)&sv[t * 16];
            u64 acc = 0ull;
            if (o < 64) {
                const float* hb = &sh1[(t * 16) * SH2S + o];
#pragma unroll
                for (int e2 = 0; e2 < 8; e2++) {
                    u64 w = mul2(ar2[e2], sv2[e2]);
                    acc = ff2(w, pk2(hb[(2*e2)*SH2S], hb[(2*e2+1)*SH2S]), acc);
                }
            } else {
                const float4* fr = (const float4*)&fijT[(t * 64 + (o - 64)) * FT2];
#pragma unroll
                for (int k = 0; k < 4; k++) {
                    float4 f = fr[k];
                    acc = ff2(mul2(ar2[2*k],   sv2[2*k]),   pk2(f.x, f.y), acc);
                    acc = ff2(mul2(ar2[2*k+1], sv2[2*k+1]), pk2(f.z, f.w), acc);
                }
            }
            float2 v = upk(acc);
            g_agg[(size_t)(t0 + t) * 128 + o] = v.x + v.y;
        }
        __syncthreads();
    }
}

// ---------------------------------------------------------------------------
// gemm2: h2 = relu(g_agg @ Wg + bg). T=32, thread=(tg16,q32)x2 targets.
// ---------------------------------------------------------------------------
#define G2_DYN_FLOATS (128*128 + 32*128)

__global__ void __launch_bounds__(512, 2)
gemm2_kernel(const float* __restrict__ Wg, const float* __restrict__ bg) {
    extern __shared__ float smem[];
    float* sWg  = smem;
    float* sagg = smem + 16384;
    __shared__ float sbg[128];

    int tid = threadIdx.x;
    for (int i = tid; i < 16384; i += 512) sWg[i] = Wg[i];
    if (tid < 128) sbg[tid] = bg[tid];
    __syncthreads();

    for (int t0 = blockIdx.x * 32; t0 < NN2; t0 += gridDim.x * 32) {
#pragma unroll
        for (int k = 0; k < 8; k++)
            sagg[tid + 512*k] = g_agg[(size_t)t0 * 128 + tid + 512*k];
        __syncthreads();

        int tg = tid >> 5;
        int q  = tid & 31;
        const float* a0p = &sagg[(2*tg + 0) * 128];
        const float* a1p = &sagg[(2*tg + 1) * 128];
        const float4* W4 = (const float4*)sWg;

        u64 acc[4];
#pragma unroll
        for (int j = 0; j < 4; j++) acc[j] = 0ull;
#pragma unroll 4
        for (int i = 0; i < 128; i++) {
            float4 w = W4[i * 32 + q];
            u64 wlo = pk2(w.x, w.y), whi = pk2(w.z, w.w);
            u64 x0 = pk1(a0p[i]), x1 = pk1(a1p[i]);
            acc[0] = ff2(x0, wlo, acc[0]); acc[1] = ff2(x0, whi, acc[1]);
            acc[2] = ff2(x1, wlo, acc[2]); acc[3] = ff2(x1, whi, acc[3]);
        }
        int o = 4 * q;
        u64 bb0 = pk2(sbg[o], sbg[o+1]), bb1 = pk2(sbg[o+2], sbg[o+3]);
#pragma unroll
        for (int tt = 0; tt < 2; tt++) {
            float2 v0 = upk(add2(acc[tt*2],   bb0));
            float2 v1 = upk(add2(acc[tt*2+1], bb1));
            float* op = &g_h2[(size_t)(t0 + 2*tg + tt) * 128 + o];
            op[0] = fmaxf(v0.x, 0.f);
            op[1] = fmaxf(v0.y, 0.f);
            op[2] = fmaxf(v1.x, 0.f);
            op[3] = fmaxf(v1.y, 0.f);
        }
        __syncthreads();
    }
}

// ---------------------------------------------------------------------------
// tail: T=16 targets/iter, thread=(pair8, q32, ihalf2), float4 weights,
// 2 targets per thread, shfl-xor(1) half-reduce. 512 threads, grid 296.
// ---------------------------------------------------------------------------
#define TAIL_DYN_FLOATS (128*128 + 64*128 + 16*128 + 16*64)

__global__ void __launch_bounds__(512, 2)
tail_kernel(const float* __restrict__ x,
            const int*   __restrict__ idx1,
            const int*   __restrict__ idx2,
            const float* __restrict__ Wup, const float* __restrict__ bup,
            const float* __restrict__ Wsc, const float* __restrict__ bsc,
            float* __restrict__ out) {
    extern __shared__ float smem[];
    float* sWup = smem;                       // 16384
    float* sWsc = smem + 16384;               // 8192
    float* sh2  = smem + 24576;               // 16*128
    float* sx   = smem + 24576 + 16*128;      // 16*64

    __shared__ float sbup[128], sbsc[128];

    int tid = threadIdx.x;
    for (int i = tid; i < 16384; i += 512) sWup[i] = Wup[i];
    for (int i = tid; i < 8192;  i += 512) sWsc[i] = Wsc[i];
    if (tid < 128) { sbup[tid] = bup[tid]; sbsc[tid] = bsc[tid]; }
    __syncthreads();

    const float4* Wu4 = (const float4*)sWup;
    const float4* Ws4 = (const float4*)sWsc;

    for (int t0 = blockIdx.x * 16; t0 < NN2; t0 += gridDim.x * 16) {
#pragma unroll
        for (int k = 0; k < 4; k++)
            sh2[tid + 512*k] = g_h2[(size_t)t0 * 128 + tid + 512*k];
        {
            int t = tid >> 5, f2 = tid & 31;
            int xr = idx1[idx2[t0 + t]];
            const float2* xp = (const float2*)&x[(size_t)xr * 64];
            ((float2*)&sx[t * 64])[f2] = xp[f2];
        }
        __syncthreads();

        int tg = tid >> 6;
        int q  = (tid >> 1) & 31;
        int c  = tid & 1;
        const float* h0 = &sh2[(2*tg + 0) * 128];
        const float* h1 = &sh2[(2*tg + 1) * 128];
        const float* x0 = &sx[(2*tg + 0) * 64];
        const float* x1 = &sx[(2*tg + 1) * 64];

        u64 ua[4], sa[4];
#pragma unroll
        for (int j = 0; j < 4; j++) { ua[j] = 0ull; sa[j] = 0ull; }
#pragma unroll 4
        for (int ii = 0; ii < 64; ii++) {
            int i = c * 64 + ii;
            float4 w = Wu4[i * 32 + q];
            u64 wlo = pk2(w.x, w.y), whi = pk2(w.z, w.w);
            u64 a0 = pk1(h0[i]), a1 = pk1(h1[i]);
            ua[0] = ff2(a0, wlo, ua[0]); ua[1] = ff2(a0, whi, ua[1]);
            ua[2] = ff2(a1, wlo, ua[2]); ua[3] = ff2(a1, whi, ua[3]);
        }
#pragma unroll 4
        for (int ii = 0; ii < 32; ii++) {
            int i = c * 32 + ii;
            float4 w = Ws4[i * 32 + q];
            u64 wlo = pk2(w.x, w.y), whi = pk2(w.z, w.w);
            u64 a0 = pk1(x0[i]), a1 = pk1(x1[i]);
            sa[0] = ff2(a0, wlo, sa[0]); sa[1] = ff2(a0, whi, sa[1]);
            sa[2] = ff2(a1, wlo, sa[2]); sa[3] = ff2(a1, whi, sa[3]);
        }
#pragma unroll
        for (int j = 0; j < 4; j++) {
            ua[j] = add2(ua[j], __shfl_xor_sync(0xFFFFFFFFu, ua[j], 1));
            sa[j] = add2(sa[j], __shfl_xor_sync(0xFFFFFFFFu, sa[j], 1));
        }
        if (c == 0) {
            int o = 4 * q;
            u64 bu0 = pk2(sbup[o], sbup[o+1]), bu1 = pk2(sbup[o+2], sbup[o+3]);
            u64 bs0 = pk2(sbsc[o], sbsc[o+1]), bs1 = pk2(sbsc[o+2], sbsc[o+3]);
#pragma unroll
            for (int tt = 0; tt < 2; tt++) {
                float2 a0 = upk(add2(ua[tt*2],   bu0));
                float2 a1 = upk(add2(ua[tt*2+1], bu1));
                float2 c0 = upk(add2(sa[tt*2],   bs0));
                float2 c1 = upk(add2(sa[tt*2+1], bs1));
                float* opt = &out[(size_t)(t0 + 2*tg + tt) * 128 + o];
                opt[0] = fmaxf(fmaxf(a0.x, 0.f) + fmaxf(c0.x, 0.f), 0.f);
                opt[1] = fmaxf(fmaxf(a0.y, 0.f) + fmaxf(c0.y, 0.f), 0.f);
                opt[2] = fmaxf(fmaxf(a1.x, 0.f) + fmaxf(c1.x, 0.f), 0.f);
                opt[3] = fmaxf(fmaxf(a1.y, 0.f) + fmaxf(c1.y, 0.f), 0.f);
            }
        }
        __syncthreads();
    }
}

// ---------------------------------------------------------------------------
extern "C" void kernel_launch(void* const* d_in, const int* in_sizes, int n_in,
                              void* d_out, int out_size) {
    const float* x      = (const float*)d_in[0];
    const float* pos    = (const float*)d_in[1];
    const float* W_down = (const float*)d_in[2];
    const float* b_down = (const float*)d_in[3];
    const float* W_pp1  = (const float*)d_in[4];
    const float* b_pp1  = (const float*)d_in[5];
    const float* W_att1 = (const float*)d_in[6];
    const float* b_att1 = (const float*)d_in[7];
    const float* W_g1   = (const float*)d_in[8];
    const float* b_g1   = (const float*)d_in[9];
    const float* W_pp2  = (const float*)d_in[10];
    const float* b_pp2  = (const float*)d_in[11];
    const float* W_att2 = (const float*)d_in[12];
    const float* b_att2 = (const float*)d_in[13];
    const float* W_g2   = (const float*)d_in[14];
    const float* b_g2   = (const float*)d_in[15];
    const float* W_up   = (const float*)d_in[16];
    const float* b_up   = (const float*)d_in[17];
    const float* W_sc   = (const float*)d_in[18];
    const float* b_sc   = (const float*)d_in[19];
    const int*   idx1   = (const int*)d_in[20];
    const int*   idx2   = (const int*)d_in[21];
    const int*   src1   = (const int*)d_in[22];
    const int*   src2   = (const int*)d_in[24];
    float* out = (float*)d_out;

    cudaFuncSetAttribute(conv1_kernel, cudaFuncAttributeMaxDynamicSharedMemorySize,
                         C1_DYN_FLOATS * (int)sizeof(float));
    cudaFuncSetAttribute(gemm_hw2_kernel, cudaFuncAttributeMaxDynamicSharedMemorySize,
                         GHW2_DYN_FLOATS * (int)sizeof(float));
    cudaFuncSetAttribute(conv2_kernel, cudaFuncAttributeMaxDynamicSharedMemorySize,
                         C2_DYN_FLOATS * (int)sizeof(float));
    cudaFuncSetAttribute(gemm2_kernel, cudaFuncAttributeMaxDynamicSharedMemorySize,
                         G2_DYN_FLOATS * (int)sizeof(float));
    cudaFuncSetAttribute(tail_kernel, cudaFuncAttributeMaxDynamicSharedMemorySize,
                         TAIL_DYN_FLOATS * (int)sizeof(float));

    down_kernel<<<128, 512>>>(x, W_down, b_down, W_att1);
    conv1_kernel<<<296, 512, C1_DYN_FLOATS * sizeof(float)>>>(
        pos, idx1, src1, W_pp1, b_pp1, W_att1, b_att1, W_g1, b_g1);
    gemm_hw2_kernel<<<296, 512, GHW2_DYN_FLOATS * sizeof(float)>>>(W_att2);
    conv2_kernel<<<296, 512, C2_DYN_FLOATS * sizeof(float)>>>(
        pos, idx1, idx2, src2, W_pp2, b_pp2, W_att2, b_att2);
    gemm2_kernel<<<296, 512, G2_DYN_FLOATS * sizeof(float)>>>(W_g2, b_g2);
    tail_kernel<<<296, 512, TAIL_DYN_FLOATS * sizeof(float)>>>(
        x, idx1, idx2, W_up, b_up, W_sc, b_sc, out);
}

// round 17
// speedup vs baseline: 1.0542x; 1.0014x over previous
#include <cuda_runtime.h>
#include <math.h>

#define NPTS 65536
#define NN1  16384
#define NN2  8192
#define KNN  16

typedef unsigned long long u64;

__device__ __forceinline__ u64 pk2(float lo, float hi) {
    u64 r; asm("mov.b64 %0,{%1,%2};" : "=l"(r) : "f"(lo), "f"(hi)); return r;
}
__device__ __forceinline__ u64 pk1(float v) { return pk2(v, v); }
__device__ __forceinline__ float2 upk(u64 v) {
    float2 f; asm("mov.b64 {%0,%1},%2;" : "=f"(f.x), "=f"(f.y) : "l"(v)); return f;
}
__device__ __forceinline__ u64 ff2(u64 a, u64 b, u64 c) {
    u64 d; asm("fma.rn.f32x2 %0,%1,%2,%3;" : "=l"(d) : "l"(a), "l"(b), "l"(c)); return d;
}
__device__ __forceinline__ u64 add2(u64 a, u64 b) {
    u64 d; asm("add.rn.f32x2 %0,%1,%2;" : "=l"(d) : "l"(a), "l"(b)); return d;
}
__device__ __forceinline__ u64 mul2(u64 a, u64 b) {
    u64 d; asm("mul.rn.f32x2 %0,%1,%2;" : "=l"(d) : "l"(a), "l"(b)); return d;
}

// Intermediate activations (device globals — no allocation allowed)
__device__ float g_h  [NPTS * 32];
__device__ float g_hW1[(size_t)NPTS * 64];    // h @ Watt1_top (rows 0..31)
__device__ float g_h1 [(size_t)NN1 * 64];
__device__ float g_hW2[(size_t)NN1 * 128];    // h1 @ Watt2_top (rows 0..63)
__device__ float g_agg[(size_t)NN2 * 128];
__device__ float g_h2 [(size_t)NN2 * 128];

// ---------------------------------------------------------------------------
// down: h = relu(x @ W_down + b_down); hW1 = h @ Watt1_top (no bias/relu)
// ---------------------------------------------------------------------------
__global__ void __launch_bounds__(512)
down_kernel(const float* __restrict__ x,
            const float* __restrict__ W,
            const float* __restrict__ b,
            const float* __restrict__ Watt1) {
    __shared__ float sW[64 * 32];
    __shared__ float sWt[32 * 64];
    __shared__ float sb[32];
    int tid = threadIdx.x;
    for (int i = tid; i < 64 * 32; i += 512) { sW[i] = W[i]; sWt[i] = Watt1[i]; }
    if (tid < 32) sb[tid] = b[tid];
    __syncthreads();

    int p = blockIdx.x * 512 + tid;

    float xr[64];
    const float4* xp = (const float4*)(x + (size_t)p * 64);
#pragma unroll
    for (int i = 0; i < 16; i++) {
        float4 v = xp[i];
        xr[4*i+0] = v.x; xr[4*i+1] = v.y; xr[4*i+2] = v.z; xr[4*i+3] = v.w;
    }
    u64 acc[16];
#pragma unroll
    for (int j = 0; j < 16; j++) acc[j] = pk2(sb[2*j], sb[2*j+1]);
#pragma unroll 8
    for (int i = 0; i < 64; i++) {
        u64 xi = pk1(xr[i]);
        const u64* wr = (const u64*)&sW[i * 32];
#pragma unroll
        for (int j = 0; j < 16; j++) acc[j] = ff2(xi, wr[j], acc[j]);
    }
    float h[32];
    float* op = &g_h[(size_t)p * 32];
#pragma unroll
    for (int j = 0; j < 16; j++) {
        float2 v = upk(acc[j]);
        h[2*j]   = fmaxf(v.x, 0.f);
        h[2*j+1] = fmaxf(v.y, 0.f);
        op[2*j]   = h[2*j];
        op[2*j+1] = h[2*j+1];
    }
    u64* wop = (u64*)&g_hW1[(size_t)p * 64];
#pragma unroll
    for (int half = 0; half < 2; half++) {
        u64 acc2[16];
#pragma unroll
        for (int j = 0; j < 16; j++) acc2[j] = 0ull;
#pragma unroll 8
        for (int i = 0; i < 32; i++) {
            u64 xi = pk1(h[i]);
            const u64* wr = (const u64*)&sWt[i * 64 + half * 32];
#pragma unroll
            for (int j = 0; j < 16; j++) acc2[j] = ff2(xi, wr[j], acc2[j]);
        }
#pragma unroll
        for (int j = 0; j < 16; j++) wop[half * 16 + j] = acc2[j];
    }
}

// ---------------------------------------------------------------------------
// conv1: T=8 targets/iter, 512 threads, grid 296, occ 2.
// ---------------------------------------------------------------------------
#define FT1  20
#define FT1A 18
#define SH1S 36
#define C1_DYN_FLOATS (320 + 2048 + 4096 + 8*32*FT1 + 8*64*FT1A + 8*16*SH1S)

__global__ void __launch_bounds__(512, 2)
conv1_kernel(const float* __restrict__ pos,
             const int*   __restrict__ idx1,
             const int*   __restrict__ src1,
             const float* __restrict__ Wpp, const float* __restrict__ bpp,
             const float* __restrict__ Watt, const float* __restrict__ batt,
             const float* __restrict__ Wg,  const float* __restrict__ bg) {
    extern __shared__ float smem[];
    float* sWpp  = smem;                        // 320
    float* sWattB= smem + 320;                  // 2048 (Watt rows 32..63)
    float* sWg   = smem + 2368;                 // 4096
    float* fijT  = smem + 6464;                 // 8*32*20 [t][rij feat][edge]
    float* attT  = smem + 6464 + 8*32*FT1;      // 8*64*18 [t][o][edge]
    float* sh    = smem + 6464 + 8*32*FT1 + 8*64*FT1A;  // 8*16*36 [et][feat]

    __shared__ __align__(8) float sbpp[32];
    __shared__ float sbatt[64], sbg[64];
    __shared__ __align__(8) float sv[128];
    __shared__ float aggS[8][64];
    __shared__ int   ssrc[128];

    int tid = threadIdx.x;
    for (int i = tid; i < 320; i += 512) sWpp[i] = Wpp[i];
    for (int i = tid; i < 2048; i += 512) sWattB[i] = Watt[32*64 + i];
    for (int i = tid; i < 4096; i += 512) sWg[i] = Wg[i];
    if (tid < 32) sbpp[tid] = bpp[tid];
    if (tid < 64) { sbatt[tid] = batt[tid]; sbg[tid] = bg[tid]; }
    __syncthreads();

    for (int t0 = blockIdx.x * 8; t0 < NN1; t0 += gridDim.x * 8) {
        // ---- gather: e fastest; h row-major + rij (vectorized); record src ----
        {
            int e   = tid & 15;
            int r   = tid >> 4;
            int t   = r >> 2;
            int sub = r & 3;
            int et  = t * 16 + e;
            int tgt = t0 + t;
            int pi = idx1[tgt];
            float pix = pos[pi*3+0], piy = pos[pi*3+1], piz = pos[pi*3+2];
            int s = src1[tgt * KNN + e];
            if (sub == 0) ssrc[et] = s;
            float pjx = pos[s*3+0], pjy = pos[s*3+1], pjz = pos[s*3+2];
            float vx = pix - pjx, vy = piy - pjy, vz = piz - pjz;
            float rel[10];
            rel[0] = pix; rel[1] = piy; rel[2] = piz;
            rel[3] = pjx; rel[4] = pjy; rel[5] = pjz;
            rel[6] = vx;  rel[7] = vy;  rel[8] = vz;
            rel[9] = sqrtf(vx*vx + vy*vy + vz*vz);

            const float4* hp = (const float4*)&g_h[(size_t)s * 32 + sub * 8];
            float4* shp = (float4*)&sh[et * SH1S + sub * 8];
            shp[0] = hp[0]; shp[1] = hp[1];

            u64 pa[4];
            const u64* bp = (const u64*)&sbpp[sub * 8];
#pragma unroll
            for (int j = 0; j < 4; j++) pa[j] = bp[j];
#pragma unroll
            for (int i = 0; i < 10; i++) {
                u64 xi = pk1(rel[i]);
                const u64* wr = (const u64*)&sWpp[i * 32 + sub * 8];
#pragma unroll
                for (int j = 0; j < 4; j++) pa[j] = ff2(xi, wr[j], pa[j]);
            }
            float* fd = &fijT[(t * 32 + sub * 8) * FT1 + e];
#pragma unroll
            for (int j = 0; j < 4; j++) {
                float2 v = upk(pa[j]);
                fd[(2*j)   * FT1] = fmaxf(v.x, 0.f);
                fd[(2*j+1) * FT1] = fmaxf(v.y, 0.f);
            }
        }
        __syncthreads();

        // ---- att: LDG issued first, FFMA loop, hW added after (hidden) ----
        {
            int t = tid >> 6;
            int q = (tid >> 2) & 15;
            int g = tid & 3;
            int eb = t * 16 + 4 * g;
            int s0 = ssrc[eb], s1 = ssrc[eb+1], s2 = ssrc[eb+2], s3 = ssrc[eb+3];
            float4 v0 = *(const float4*)&g_hW1[(size_t)s0 * 64 + 4*q];
            float4 v1 = *(const float4*)&g_hW1[(size_t)s1 * 64 + 4*q];
            float4 v2 = *(const float4*)&g_hW1[(size_t)s2 * 64 + 4*q];
            float4 v3 = *(const float4*)&g_hW1[(size_t)s3 * 64 + 4*q];

            u64 acc[8];
#pragma unroll
            for (int j = 0; j < 8; j++) acc[j] = 0ull;
            const float4* W4 = (const float4*)sWattB;
            const float* fb = &fijT[(t * 32) * FT1 + 4 * g];
#pragma unroll 8
            for (int i = 0; i < 32; i++) {
                float4 w = W4[i * 16 + q];
                u64 w0 = pk1(w.x), w1 = pk1(w.y), w2 = pk1(w.z), w3 = pk1(w.w);
                ulonglong2 a = *(const ulonglong2*)(fb + i * FT1);
                acc[0] = ff2(a.x, w0, acc[0]); acc[1] = ff2(a.y, w0, acc[1]);
                acc[2] = ff2(a.x, w1, acc[2]); acc[3] = ff2(a.y, w1, acc[3]);
                acc[4] = ff2(a.x, w2, acc[4]); acc[5] = ff2(a.y, w2, acc[5]);
                acc[6] = ff2(a.x, w3, acc[6]); acc[7] = ff2(a.y, w3, acc[7]);
            }
            acc[0] = add2(acc[0], pk2(v0.x, v1.x)); acc[1] = add2(acc[1], pk2(v2.x, v3.x));
            acc[2] = add2(acc[2], pk2(v0.y, v1.y)); acc[3] = add2(acc[3], pk2(v2.y, v3.y));
            acc[4] = add2(acc[4], pk2(v0.z, v1.z)); acc[5] = add2(acc[5], pk2(v2.z, v3.z));
            acc[6] = add2(acc[6], pk2(v0.w, v1.w)); acc[7] = add2(acc[7], pk2(v2.w, v3.w));
            float* ab = &attT[(t * 64 + 4 * q) * FT1A + 4 * g];
#pragma unroll
            for (int j = 0; j < 4; j++) {
                u64 bb = pk1(sbatt[4*q + j]);
                float2 r0 = upk(add2(acc[j*2],   bb));
                float2 r1 = upk(add2(acc[j*2+1], bb));
                *(u64*)&ab[j*FT1A + 0] = pk2(fmaxf(r0.x, 0.f), fmaxf(r0.y, 0.f));
                *(u64*)&ab[j*FT1A + 2] = pk2(fmaxf(r1.x, 0.f), fmaxf(r1.y, 0.f));
            }
        }
        __syncthreads();

        // ---- softmax per edge: single pass, no max; exp stored in place ----
        {
            int et = tid >> 2, c = tid & 3;
            float* ac = &attT[((et >> 4) * 64) * FT1A + (et & 15)];
            float s = 0.f;
#pragma unroll 8
            for (int k = 0; k < 16; k++) {
                float ev = __expf(ac[(c + 4*k)*FT1A]);
                s += ev;
                ac[(c + 4*k)*FT1A] = ev;
            }
            s += __shfl_xor_sync(0xFFFFFFFFu, s, 1);
            s += __shfl_xor_sync(0xFFFFFFFFu, s, 2);
            if (c == 0) sv[et] = 1.f / s;
        }
        __syncthreads();

        // ---- agg[o] = sum_e (ev * inv_sum) * fij, edge-pair packed ----
        {
            int t = tid >> 6, o = tid & 63;
            const u64* ar2 = (const u64*)&attT[(t * 64 + o) * FT1A];
            const u64* sv2 = (const u64*)&sv[t * 16];
            u64 acc = 0ull;
            if (o < 32) {
                const float* hb = &sh[(t * 16) * SH1S + o];
#pragma unroll
                for (int e2 = 0; e2 < 8; e2++) {
                    u64 w = mul2(ar2[e2], sv2[e2]);
                    acc = ff2(w, pk2(hb[(2*e2)*SH1S], hb[(2*e2+1)*SH1S]), acc);
                }
            } else {
                const float4* fr = (const float4*)&fijT[(t * 32 + (o - 32)) * FT1];
#pragma unroll
                for (int k = 0; k < 4; k++) {
                    float4 f = fr[k];
                    acc = ff2(mul2(ar2[2*k],   sv2[2*k]),   pk2(f.x, f.y), acc);
                    acc = ff2(mul2(ar2[2*k+1], sv2[2*k+1]), pk2(f.z, f.w), acc);
                }
            }
            float2 v = upk(acc);
            aggS[t][o] = v.x + v.y;
        }
        __syncthreads();

        // ---- global: h1 = relu(agg @ Wg + bg): (t8, op32, c2), shfl ----
        {
            int t = tid >> 6, op = (tid >> 1) & 31, c = tid & 1;
            u64 acc = 0ull;
#pragma unroll 8
            for (int ii = 0; ii < 32; ii++) {
                int i = c * 32 + ii;
                acc = ff2(pk1(aggS[t][i]), *(const u64*)&sWg[i*64 + 2*op], acc);
            }
            u64 other = __shfl_xor_sync(0xFFFFFFFFu, acc, 1);
            acc = add2(acc, other);
            if (c == 0) {
                float2 v = upk(acc);
                int o = 2 * op;
                float* opt = &g_h1[(size_t)(t0 + t) * 64 + o];
                opt[0] = fmaxf(v.x + sbg[o],   0.f);
                opt[1] = fmaxf(v.y + sbg[o+1], 0.f);
            }
        }
        __syncthreads();
    }
}

// ---------------------------------------------------------------------------
// gemm_hw2: g_hW2 = g_h1 @ Watt2_top  [16384,64]@[64,128]
// ---------------------------------------------------------------------------
#define GHW2_DYN_FLOATS (64*128 + 32*64)

__global__ void __launch_bounds__(512, 2)
gemm_hw2_kernel(const float* __restrict__ Watt2) {
    extern __shared__ float smem[];
    float* sW   = smem;
    float* sact = smem + 64*128;

    int tid = threadIdx.x;
    for (int i = tid; i < 64*128; i += 512) sW[i] = Watt2[i];
    __syncthreads();

    for (int t0 = blockIdx.x * 32; t0 < NN1; t0 += gridDim.x * 32) {
        ((float4*)sact)[tid] = ((const float4*)&g_h1[(size_t)t0 * 64])[tid];
        __syncthreads();

        int tg = tid >> 5;
        int q  = tid & 31;
        const float* a0p = &sact[(2*tg + 0) * 64];
        const float* a1p = &sact[(2*tg + 1) * 64];
        const float4* W4 = (const float4*)sW;

        u64 acc[4];
#pragma unroll
        for (int j = 0; j < 4; j++) acc[j] = 0ull;
#pragma unroll 8
        for (int i = 0; i < 64; i++) {
            float4 w = W4[i * 32 + q];
            u64 wlo = pk2(w.x, w.y), whi = pk2(w.z, w.w);
            u64 x0 = pk1(a0p[i]), x1 = pk1(a1p[i]);
            acc[0] = ff2(x0, wlo, acc[0]); acc[1] = ff2(x0, whi, acc[1]);
            acc[2] = ff2(x1, wlo, acc[2]); acc[3] = ff2(x1, whi, acc[3]);
        }
        int o = 4 * q;
        u64* o0 = (u64*)&g_hW2[(size_t)(t0 + 2*tg) * 128 + o];
        u64* o1 = (u64*)&g_hW2[(size_t)(t0 + 2*tg + 1) * 128 + o];
        o0[0] = acc[0]; o0[1] = acc[1];
        o1[0] = acc[2]; o1[1] = acc[3];
        __syncthreads();
    }
}

// ---------------------------------------------------------------------------
// conv2: T=4 targets/iter, 512 threads, grid 296, occ 2.
// ---------------------------------------------------------------------------
#define FT2   20
#define FT2A  18
#define SH2S  68
#define C2_DYN_FLOATS (640 + 8192 + 4*64*FT2 + 4*128*FT2A + 4*16*SH2S)

__global__ void __launch_bounds__(512, 2)
conv2_kernel(const float* __restrict__ pos,
             const int*   __restrict__ idx1,
             const int*   __restrict__ idx2,
             const int*   __restrict__ src2,
             const float* __restrict__ Wpp, const float* __restrict__ bpp,
             const float* __restrict__ Watt, const float* __restrict__ batt) {
    extern __shared__ float smem[];
    float* sWpp  = smem;                                // 640
    float* sWattB= smem + 640;                          // 8192 (rows 64..127)
    float* fijT  = smem + 640 + 8192;                   // 4*64*20
    float* attT  = smem + 640 + 8192 + 4*64*FT2;        // 4*128*18
    float* sh1   = smem + 640 + 8192 + 4*64*FT2 + 4*128*FT2A;  // 4*16*68

    __shared__ __align__(8) float sbpp[64];
    __shared__ float sbatt[128];
    __shared__ __align__(8) float sv[64];
    __shared__ int   ssrc[64];

    int tid = threadIdx.x;
    for (int i = tid; i < 640; i += 512) sWpp[i] = Wpp[i];
    for (int i = tid; i < 8192; i += 512) sWattB[i] = Watt[64*128 + i];
    if (tid < 64)  sbpp[tid] = bpp[tid];
    if (tid < 128) sbatt[tid] = batt[tid];
    __syncthreads();

    for (int t0 = blockIdx.x * 4; t0 < NN2; t0 += gridDim.x * 4) {
        // ---- gather: e fastest; h1 row-major + rij (vectorized); record src ----
        {
            int e   = tid & 15;
            int idx = tid >> 4;
            int t   = idx >> 3;
            int sub = idx & 7;
            int et  = t * 16 + e;
            int tgt = t0 + t;
            int pidx = idx1[idx2[tgt]];
            float pix = pos[pidx*3+0], piy = pos[pidx*3+1], piz = pos[pidx*3+2];
            int s = src2[tgt * KNN + e];
            if (sub == 0) ssrc[et] = s;
            int pj = idx1[s];
            float pjx = pos[pj*3+0], pjy = pos[pj*3+1], pjz = pos[pj*3+2];
            float vx = pix - pjx, vy = piy - pjy, vz = piz - pjz;
            float rel[10];
            rel[0] = pix; rel[1] = piy; rel[2] = piz;
            rel[3] = pjx; rel[4] = pjy; rel[5] = pjz;
            rel[6] = vx;  rel[7] = vy;  rel[8] = vz;
            rel[9] = sqrtf(vx*vx + vy*vy + vz*vz);

            const float4* hp = (const float4*)&g_h1[(size_t)s * 64 + sub * 8];
            float4* shp = (float4*)&sh1[et * SH2S + sub * 8];
            shp[0] = hp[0]; shp[1] = hp[1];

            u64 pa[4];
            const u64* bp = (const u64*)&sbpp[sub * 8];
#pragma unroll
            for (int j = 0; j < 4; j++) pa[j] = bp[j];
#pragma unroll
            for (int i = 0; i < 10; i++) {
                u64 xi = pk1(rel[i]);
                const u64* wr = (const u64*)&sWpp[i * 64 + sub * 8];
#pragma unroll
                for (int j = 0; j < 4; j++) pa[j] = ff2(xi, wr[j], pa[j]);
            }
            float* fd = &fijT[(t * 64 + sub * 8) * FT2 + e];
#pragma unroll
            for (int j = 0; j < 4; j++) {
                float2 v = upk(pa[j]);
                fd[(2*j)   * FT2] = fmaxf(v.x, 0.f);
                fd[(2*j+1) * FT2] = fmaxf(v.y, 0.f);
            }
        }
        __syncthreads();

        // ---- att: LDG issued first, FFMA loop, hW added after (hidden) ----
        {
            int g  = tid & 3;
            int ql = (tid >> 2) & 7;
            int t  = (tid >> 5) & 3;
            int qh = tid >> 7;
            int q  = ql + 8 * qh;
            int eb = t * 16 + 4 * g;
            int s0 = ssrc[eb], s1 = ssrc[eb+1], s2 = ssrc[eb+2], s3 = ssrc[eb+3];
            float4 v0 = *(const float4*)&g_hW2[(size_t)s0 * 128 + 4*q];
            float4 v1 = *(const float4*)&g_hW2[(size_t)s1 * 128 + 4*q];
            float4 v2 = *(const float4*)&g_hW2[(size_t)s2 * 128 + 4*q];
            float4 v3 = *(const float4*)&g_hW2[(size_t)s3 * 128 + 4*q];

            u64 acc[8];
#pragma unroll
            for (int j = 0; j < 8; j++) acc[j] = 0ull;
            const float4* W4 = (const float4*)sWattB;
            const float* fb = &fijT[(t * 64) * FT2 + 4 * g];
#pragma unroll 8
            for (int i = 0; i < 64; i++) {
                float4 w = W4[i * 32 + q];
                u64 w0 = pk1(w.x), w1 = pk1(w.y), w2 = pk1(w.z), w3 = pk1(w.w);
                ulonglong2 a = *(const ulonglong2*)(fb + i * FT2);
                acc[0] = ff2(a.x, w0, acc[0]); acc[1] = ff2(a.y, w0, acc[1]);
                acc[2] = ff2(a.x, w1, acc[2]); acc[3] = ff2(a.y, w1, acc[3]);
                acc[4] = ff2(a.x, w2, acc[4]); acc[5] = ff2(a.y, w2, acc[5]);
                acc[6] = ff2(a.x, w3, acc[6]); acc[7] = ff2(a.y, w3, acc[7]);
            }
            acc[0] = add2(acc[0], pk2(v0.x, v1.x)); acc[1] = add2(acc[1], pk2(v2.x, v3.x));
            acc[2] = add2(acc[2], pk2(v0.y, v1.y)); acc[3] = add2(acc[3], pk2(v2.y, v3.y));
            acc[4] = add2(acc[4], pk2(v0.z, v1.z)); acc[5] = add2(acc[5], pk2(v2.z, v3.z));
            acc[6] = add2(acc[6], pk2(v0.w, v1.w)); acc[7] = add2(acc[7], pk2(v2.w, v3.w));
            float* ab = &attT[(t * 128 + 4 * q) * FT2A + 4 * g];
#pragma unroll
            for (int j = 0; j < 4; j++) {
                u64 bb = pk1(sbatt[4*q + j]);
                float2 r0 = upk(add2(acc[j*2],   bb));
                float2 r1 = upk(add2(acc[j*2+1], bb));
                *(u64*)&ab[j*FT2A + 0] = pk2(fmaxf(r0.x, 0.f), fmaxf(r0.y, 0.f));
                *(u64*)&ab[j*FT2A + 2] = pk2(fmaxf(r1.x, 0.f), fmaxf(r1.y, 0.f));
            }
        }
        __syncthreads();

        // ---- softmax per edge: single pass, no max; exp stored in place ----
        {
            int et = tid >> 3, cc = tid & 7;
            float* ac = &attT[((et >> 4) * 128) * FT2A + (et & 15)];
            float s = 0.f;
#pragma unroll 8
            for (int k = 0; k < 16; k++) {
                float ev = __expf(ac[(cc + 8*k)*FT2A]);
                s += ev;
                ac[(cc + 8*k)*FT2A] = ev;
            }
            s += __shfl_xor_sync(0xFFFFFFFFu, s, 1);
            s += __shfl_xor_sync(0xFFFFFFFFu, s, 2);
            s += __shfl_xor_sync(0xFFFFFFFFu, s, 4);
            if (cc == 0) sv[et] = 1.f / s;
        }
        __syncthreads();

        // ---- agg -> global scratch, edge-pair packed ----
        {
            int t = tid >> 7, o = tid & 127;
            const u64* ar2 = (const u64*)&attT[(t * 128 + o) * FT2A];
            const u64* sv2 = (const u64*)&sv[t * 16];
            u64 acc = 0ull;
            if (o < 64) {
                const float* hb = &sh1[(t * 16) * SH2S + o];
#pragma unroll
                for (int e2 = 0; e2 < 8; e2++) {
                    u64 w = mul2(ar2[e2], sv2[e2]);
                    acc = ff2(w, pk2(hb[(2*e2)*SH2S], hb[(2*e2+1)*SH2S]), acc);
                }
            } else {
                const float4* fr = (const float4*)&fijT[(t * 64 + (o - 64)) * FT2];
#pragma unroll
                for (int k = 0; k < 4; k++) {
                    float4 f = fr[k];
                    acc = ff2(mul2(ar2[2*k],   sv2[2*k]),   pk2(f.x, f.y), acc);
                    acc = ff2(mul2(ar2[2*k+1], sv2[2*k+1]), pk2(f.z, f.w), acc);
                }
            }
            float2 v = upk(acc);
            g_agg[(size_t)(t0 + t) * 128 + o] = v.x + v.y;
        }
        __syncthreads();
    }
}

// ---------------------------------------------------------------------------
// gemm2: h2 = relu(g_agg @ Wg + bg). T=32, thread=(tg16,q32)x2 targets.
// ---------------------------------------------------------------------------
#define G2_DYN_FLOATS (128*128 + 32*128)

__global__ void __launch_bounds__(512, 2)
gemm2_kernel(const float* __restrict__ Wg, const float* __restrict__ bg) {
    extern __shared__ float smem[];
    float* sWg  = smem;
    float* sagg = smem + 16384;
    __shared__ float sbg[128];

    int tid = threadIdx.x;
    for (int i = tid; i < 16384; i += 512) sWg[i] = Wg[i];
    if (tid < 128) sbg[tid] = bg[tid];
    __syncthreads();

    for (int t0 = blockIdx.x * 32; t0 < NN2; t0 += gridDim.x * 32) {
#pragma unroll
        for (int k = 0; k < 8; k++)
            sagg[tid + 512*k] = g_agg[(size_t)t0 * 128 + tid + 512*k];
        __syncthreads();

        int tg = tid >> 5;
        int q  = tid & 31;
        const float* a0p = &sagg[(2*tg + 0) * 128];
        const float* a1p = &sagg[(2*tg + 1) * 128];
        const float4* W4 = (const float4*)sWg;

        u64 acc[4];
#pragma unroll
        for (int j = 0; j < 4; j++) acc[j] = 0ull;
#pragma unroll 8
        for (int i = 0; i < 128; i++) {
            float4 w = W4[i * 32 + q];
            u64 wlo = pk2(w.x, w.y), whi = pk2(w.z, w.w);
            u64 x0 = pk1(a0p[i]), x1 = pk1(a1p[i]);
            acc[0] = ff2(x0, wlo, acc[0]); acc[1] = ff2(x0, whi, acc[1]);
            acc[2] = ff2(x1, wlo, acc[2]); acc[3] = ff2(x1, whi, acc[3]);
        }
        int o = 4 * q;
        u64 bb0 = pk2(sbg[o], sbg[o+1]), bb1 = pk2(sbg[o+2], sbg[o+3]);
#pragma unroll
        for (int tt = 0; tt < 2; tt++) {
            float2 v0 = upk(add2(acc[tt*2],   bb0));
            float2 v1 = upk(add2(acc[tt*2+1], bb1));
            float* op = &g_h2[(size_t)(t0 + 2*tg + tt) * 128 + o];
            op[0] = fmaxf(v0.x, 0.f);
            op[1] = fmaxf(v0.y, 0.f);
            op[2] = fmaxf(v1.x, 0.f);
            op[3] = fmaxf(v1.y, 0.f);
        }
        __syncthreads();
    }
}

// ---------------------------------------------------------------------------
// tail: T=16 targets/iter, thread=(pair8, q32, ihalf2), float4 weights,
// 2 targets per thread, shfl-xor(1) half-reduce. 512 threads, grid 296.
// ---------------------------------------------------------------------------
#define TAIL_DYN_FLOATS (128*128 + 64*128 + 16*128 + 16*64)

__global__ void __launch_bounds__(512, 2)
tail_kernel(const float* __restrict__ x,
            const int*   __restrict__ idx1,
            const int*   __restrict__ idx2,
            const float* __restrict__ Wup, const float* __restrict__ bup,
            const float* __restrict__ Wsc, const float* __restrict__ bsc,
            float* __restrict__ out) {
    extern __shared__ float smem[];
    float* sWup = smem;                       // 16384
    float* sWsc = smem + 16384;               // 8192
    float* sh2  = smem + 24576;               // 16*128
    float* sx   = smem + 24576 + 16*128;      // 16*64

    __shared__ float sbup[128], sbsc[128];

    int tid = threadIdx.x;
    for (int i = tid; i < 16384; i += 512) sWup[i] = Wup[i];
    for (int i = tid; i < 8192;  i += 512) sWsc[i] = Wsc[i];
    if (tid < 128) { sbup[tid] = bup[tid]; sbsc[tid] = bsc[tid]; }
    __syncthreads();

    const float4* Wu4 = (const float4*)sWup;
    const float4* Ws4 = (const float4*)sWsc;

    for (int t0 = blockIdx.x * 16; t0 < NN2; t0 += gridDim.x * 16) {
#pragma unroll
        for (int k = 0; k < 4; k++)
            sh2[tid + 512*k] = g_h2[(size_t)t0 * 128 + tid + 512*k];
        {
            int t = tid >> 5, f2 = tid & 31;
            int xr = idx1[idx2[t0 + t]];
            const float2* xp = (const float2*)&x[(size_t)xr * 64];
            ((float2*)&sx[t * 64])[f2] = xp[f2];
        }
        __syncthreads();

        int tg = tid >> 6;
        int q  = (tid >> 1) & 31;
        int c  = tid & 1;
        const float* h0 = &sh2[(2*tg + 0) * 128];
        const float* h1 = &sh2[(2*tg + 1) * 128];
        const float* x0 = &sx[(2*tg + 0) * 64];
        const float* x1 = &sx[(2*tg + 1) * 64];

        u64 ua[4], sa[4];
#pragma unroll
        for (int j = 0; j < 4; j++) { ua[j] = 0ull; sa[j] = 0ull; }
#pragma unroll 8
        for (int ii = 0; ii < 64; ii++) {
            int i = c * 64 + ii;
            float4 w = Wu4[i * 32 + q];
            u64 wlo = pk2(w.x, w.y), whi = pk2(w.z, w.w);
            u64 a0 = pk1(h0[i]), a1 = pk1(h1[i]);
            ua[0] = ff2(a0, wlo, ua[0]); ua[1] = ff2(a0, whi, ua[1]);
            ua[2] = ff2(a1, wlo, ua[2]); ua[3] = ff2(a1, whi, ua[3]);
        }
#pragma unroll 8
        for (int ii = 0; ii < 32; ii++) {
            int i = c * 32 + ii;
            float4 w = Ws4[i * 32 + q];
            u64 wlo = pk2(w.x, w.y), whi = pk2(w.z, w.w);
            u64 a0 = pk1(x0[i]), a1 = pk1(x1[i]);
            sa[0] = ff2(a0, wlo, sa[0]); sa[1] = ff2(a0, whi, sa[1]);
            sa[2] = ff2(a1, wlo, sa[2]); sa[3] = ff2(a1, whi, sa[3]);
        }
#pragma unroll
        for (int j = 0; j < 4; j++) {
            ua[j] = add2(ua[j], __shfl_xor_sync(0xFFFFFFFFu, ua[j], 1));
            sa[j] = add2(sa[j], __shfl_xor_sync(0xFFFFFFFFu, sa[j], 1));
        }
        if (c == 0) {
            int o = 4 * q;
            u64 bu0 = pk2(sbup[o], sbup[o+1]), bu1 = pk2(sbup[o+2], sbup[o+3]);
            u64 bs0 = pk2(sbsc[o], sbsc[o+1]), bs1 = pk2(sbsc[o+2], sbsc[o+3]);
#pragma unroll
            for (int tt = 0; tt < 2; tt++) {
                float2 a0 = upk(add2(ua[tt*2],   bu0));
                float2 a1 = upk(add2(ua[tt*2+1], bu1));
                float2 c0 = upk(add2(sa[tt*2],   bs0));
                float2 c1 = upk(add2(sa[tt*2+1], bs1));
                float* opt = &out[(size_t)(t0 + 2*tg + tt) * 128 + o];
                opt[0] = fmaxf(fmaxf(a0.x, 0.f) + fmaxf(c0.x, 0.f), 0.f);
                opt[1] = fmaxf(fmaxf(a0.y, 0.f) + fmaxf(c0.y, 0.f), 0.f);
                opt[2] = fmaxf(fmaxf(a1.x, 0.f) + fmaxf(c1.x, 0.f), 0.f);
                opt[3] = fmaxf(fmaxf(a1.y, 0.f) + fmaxf(c1.y, 0.f), 0.f);
            }
        }
        __syncthreads();
    }
}

// ---------------------------------------------------------------------------
extern "C" void kernel_launch(void* const* d_in, const int* in_sizes, int n_in,
                              void* d_out, int out_size) {
    const float* x      = (const float*)d_in[0];
    const float* pos    = (const float*)d_in[1];
    const float* W_down = (const float*)d_in[2];
    const float* b_down = (const float*)d_in[3];
    const float* W_pp1  = (const float*)d_in[4];
    const float* b_pp1  = (const float*)d_in[5];
    const float* W_att1 = (const float*)d_in[6];
    const float* b_att1 = (const float*)d_in[7];
    const float* W_g1   = (const float*)d_in[8];
    const float* b_g1   = (const float*)d_in[9];
    const float* W_pp2  = (const float*)d_in[10];
    const float* b_pp2  = (const float*)d_in[11];
    const float* W_att2 = (const float*)d_in[12];
    const float* b_att2 = (const float*)d_in[13];
    const float* W_g2   = (const float*)d_in[14];
    const float* b_g2   = (const float*)d_in[15];
    const float* W_up   = (const float*)d_in[16];
    const float* b_up   = (const float*)d_in[17];
    const float* W_sc   = (const float*)d_in[18];
    const float* b_sc   = (const float*)d_in[19];
    const int*   idx1   = (const int*)d_in[20];
    const int*   idx2   = (const int*)d_in[21];
    const int*   src1   = (const int*)d_in[22];
    const int*   src2   = (const int*)d_in[24];
    float* out = (float*)d_out;

    cudaFuncSetAttribute(conv1_kernel, cudaFuncAttributeMaxDynamicSharedMemorySize,
                         C1_DYN_FLOATS * (int)sizeof(float));
    cudaFuncSetAttribute(gemm_hw2_kernel, cudaFuncAttributeMaxDynamicSharedMemorySize,
                         GHW2_DYN_FLOATS * (int)sizeof(float));
    cudaFuncSetAttribute(conv2_kernel, cudaFuncAttributeMaxDynamicSharedMemorySize,
                         C2_DYN_FLOATS * (int)sizeof(float));
    cudaFuncSetAttribute(gemm2_kernel, cudaFuncAttributeMaxDynamicSharedMemorySize,
                         G2_DYN_FLOATS * (int)sizeof(float));
    cudaFuncSetAttribute(tail_kernel, cudaFuncAttributeMaxDynamicSharedMemorySize,
                         TAIL_DYN_FLOATS * (int)sizeof(float));

    down_kernel<<<128, 512>>>(x, W_down, b_down, W_att1);
    conv1_kernel<<<296, 512, C1_DYN_FLOATS * sizeof(float)>>>(
        pos, idx1, src1, W_pp1, b_pp1, W_att1, b_att1, W_g1, b_g1);
    gemm_hw2_kernel<<<296, 512, GHW2_DYN_FLOATS * sizeof(float)>>>(W_att2);
    conv2_kernel<<<296, 512, C2_DYN_FLOATS * sizeof(float)>>>(
        pos, idx1, idx2, src2, W_pp2, b_pp2, W_att2, b_att2);
    gemm2_kernel<<<296, 512, G2_DYN_FLOATS * sizeof(float)>>>(W_g2, b_g2);
    tail_kernel<<<296, 512, TAIL_DYN_FLOATS * sizeof(float)>>>(
        x, idx1, idx2, W_up, b_up, W_sc, b_sc, out);
}